// round 7
// baseline (speedup 1.0000x reference)
#include <cuda_runtime.h>
#include <cuda_fp16.h>
#include <math.h>

#define BATCH 4
#define SEQ   2048
#define DIM   1024
#define HEADS 16
#define HD    64
#define MTOT  (BATCH*SEQ)   // 8192

// Scratch (allocation-free rule: __device__ globals)
__device__ __half g_in [3][MTOT*DIM];     // fp16 copies of Q,K,V inputs
__device__ __half g_w  [4][DIM*DIM];      // fp16 copies of Wq,Wk,Wv,Wo
__device__ __half g_qh [MTOT*DIM];        // projected q (pre-scaled 0.125)
__device__ __half g_kh [MTOT*DIM];
__device__ __half g_vh [MTOT*DIM];
__device__ __half g_ohh[MTOT*DIM];        // attention output heads
__device__ float  g_rl [BATCH*HEADS*SEQ];
// exp(scores), FRAGMENT-BLOCKED: tile (bh,tile_t,tile_s) of 16x64 halves
// = 512 words; word addr = tile*512 + word_idx*32 + lane.
__device__ unsigned g_expa[(size_t)BATCH*HEADS*(SEQ/16)*(SEQ/64)*512];

// ---------------------------------------------------------------------------
// helpers
// ---------------------------------------------------------------------------
__device__ __forceinline__ void mma16(float c[4],
    unsigned a0, unsigned a1, unsigned a2, unsigned a3,
    unsigned b0, unsigned b1)
{
    asm volatile(
      "mma.sync.aligned.m16n8k16.row.col.f32.f16.f16.f32 "
      "{%0,%1,%2,%3},{%4,%5,%6,%7},{%8,%9},{%0,%1,%2,%3};"
      : "+f"(c[0]), "+f"(c[1]), "+f"(c[2]), "+f"(c[3])
      : "r"(a0), "r"(a1), "r"(a2), "r"(a3), "r"(b0), "r"(b1));
}
__device__ __forceinline__ void ldmx4t(unsigned r[4], unsigned addr)
{
    asm volatile(
      "ldmatrix.sync.aligned.m8n8.x4.trans.shared.b16 {%0,%1,%2,%3}, [%4];"
      : "=r"(r[0]), "=r"(r[1]), "=r"(r[2]), "=r"(r[3]) : "r"(addr));
}
__device__ __forceinline__ unsigned h2u(__half2 h) { return *(unsigned*)&h; }
__device__ __forceinline__ void cpa16(unsigned dst, const void* src) {
    asm volatile("cp.async.cg.shared.global [%0], [%1], 16;\n" :: "r"(dst), "l"(src));
}

// ---------------------------------------------------------------------------
// fp32 -> fp16 convert (grid-stride, float4 -> 2x half2)
// ---------------------------------------------------------------------------
__global__ void __launch_bounds__(256) cvt_f2h(
    const float* __restrict__ in, __half* __restrict__ out, int n4)
{
    for (int i = blockIdx.x*256 + threadIdx.x; i < n4; i += gridDim.x*256) {
        float4 f = *(const float4*)(in + (size_t)i*4);
        __half2 h0 = __floats2half2_rn(f.x, f.y);
        __half2 h1 = __floats2half2_rn(f.z, f.w);
        *(__half2*)(out + (size_t)i*4)     = h0;
        *(__half2*)(out + (size_t)i*4 + 2) = h1;
    }
}

// ---------------------------------------------------------------------------
// all-fp16 NT GEMM: C[m,n] = sum_k A[m,k]*W[n,k] + bias[n]
// Block 128x128, BK=32, 256 threads, 2-stage cp.async pipeline.
// OMODE: 0 fp32-out, 1 fp16-out, 2 fp16-out scaled 0.125.
// ---------------------------------------------------------------------------
#define LDH 40
template<int OMODE>
__global__ void __launch_bounds__(256,2) gemm_hh(
    const __half* __restrict__ A, const __half* __restrict__ W,
    const float* __restrict__ bias, void* __restrict__ Cv)
{
    __shared__ __half As[2][128*LDH];
    __shared__ __half Ws[2][128*LDH];
    const int tid  = threadIdx.x;
    const int lane = tid & 31, warp = tid >> 5;
    const int g = lane >> 2, t = lane & 3;
    const int m0 = blockIdx.y << 7, n0 = blockIdx.x << 7;
    const int wm = (warp >> 2) << 6, wn = (warp & 3) << 5;
    const __half* Ab = A + (size_t)m0 * DIM;
    const __half* Wb = W + (size_t)n0 * DIM;

    // cp.async coords: 512 16B-chunks per operand per stage, 2 per thread
    const int ch0 = tid << 1, ch1 = ch0 + 1;
    const int r0 = ch0 >> 2, c0 = (ch0 & 3) << 3;
    const int r1 = ch1 >> 2, c1 = (ch1 & 3) << 3;
    const unsigned asb[2] = { (unsigned)__cvta_generic_to_shared(As[0]),
                              (unsigned)__cvta_generic_to_shared(As[1]) };
    const unsigned wsb[2] = { (unsigned)__cvta_generic_to_shared(Ws[0]),
                              (unsigned)__cvta_generic_to_shared(Ws[1]) };

    float acc[4][4][4];
    #pragma unroll
    for (int i = 0; i < 4; i++)
        #pragma unroll
        for (int j = 0; j < 4; j++)
            #pragma unroll
            for (int v = 0; v < 4; v++) acc[i][j][v] = 0.f;

    // prologue: k-tile 0 -> stage 0
    cpa16(asb[0] + ((r0*LDH + c0) << 1), Ab + (size_t)r0 * DIM + c0);
    cpa16(asb[0] + ((r1*LDH + c1) << 1), Ab + (size_t)r1 * DIM + c1);
    cpa16(wsb[0] + ((r0*LDH + c0) << 1), Wb + (size_t)r0 * DIM + c0);
    cpa16(wsb[0] + ((r1*LDH + c1) << 1), Wb + (size_t)r1 * DIM + c1);
    asm volatile("cp.async.commit_group;\n");

    for (int kt = 0; kt < DIM/32; kt++) {
        const int st = kt & 1;
        if (kt + 1 < DIM/32) {
            const int ns = (kt + 1) & 1;
            const int k0 = (kt + 1) << 5;
            cpa16(asb[ns] + ((r0*LDH + c0) << 1), Ab + (size_t)r0 * DIM + k0 + c0);
            cpa16(asb[ns] + ((r1*LDH + c1) << 1), Ab + (size_t)r1 * DIM + k0 + c1);
            cpa16(wsb[ns] + ((r0*LDH + c0) << 1), Wb + (size_t)r0 * DIM + k0 + c0);
            cpa16(wsb[ns] + ((r1*LDH + c1) << 1), Wb + (size_t)r1 * DIM + k0 + c1);
            asm volatile("cp.async.commit_group;\n");
            asm volatile("cp.async.wait_group 1;\n");
        } else {
            asm volatile("cp.async.wait_group 0;\n");
        }
        __syncthreads();

        const __half* as = As[st];
        const __half* ws = Ws[st];
        #pragma unroll
        for (int s = 0; s < 2; s++) {
            const int kb = (s << 4) + (t << 1);
            unsigned af[4][4], bf[4][2];
            #pragma unroll
            for (int mt = 0; mt < 4; mt++) {
                int r = wm + (mt << 4) + g;
                af[mt][0] = *(const unsigned*)&as[r*LDH + kb];
                af[mt][1] = *(const unsigned*)&as[(r+8)*LDH + kb];
                af[mt][2] = *(const unsigned*)&as[r*LDH + kb + 8];
                af[mt][3] = *(const unsigned*)&as[(r+8)*LDH + kb + 8];
            }
            #pragma unroll
            for (int nt = 0; nt < 4; nt++) {
                int r = wn + (nt << 3) + g;
                bf[nt][0] = *(const unsigned*)&ws[r*LDH + kb];
                bf[nt][1] = *(const unsigned*)&ws[r*LDH + kb + 8];
            }
            #pragma unroll
            for (int mt = 0; mt < 4; mt++)
                #pragma unroll
                for (int nt = 0; nt < 4; nt++)
                    mma16(acc[mt][nt], af[mt][0], af[mt][1], af[mt][2], af[mt][3],
                          bf[nt][0], bf[nt][1]);
        }
        __syncthreads();
    }

    #pragma unroll
    for (int mt = 0; mt < 4; mt++) {
        int r = m0 + wm + (mt << 4) + g;
        #pragma unroll
        for (int nt = 0; nt < 4; nt++) {
            int c = n0 + wn + (nt << 3) + (t << 1);
            float2 bv = *(const float2*)(bias + c);
            float o00 = acc[mt][nt][0] + bv.x, o01 = acc[mt][nt][1] + bv.y;
            float o10 = acc[mt][nt][2] + bv.x, o11 = acc[mt][nt][3] + bv.y;
            if (OMODE == 0) {
                float* C = (float*)Cv;
                *(float2*)(C + (size_t)r       * DIM + c) = make_float2(o00, o01);
                *(float2*)(C + (size_t)(r + 8) * DIM + c) = make_float2(o10, o11);
            } else {
                const float sc = (OMODE == 2) ? 0.125f : 1.0f;
                __half* C = (__half*)Cv;
                *(__half2*)(C + (size_t)r       * DIM + c) = __floats2half2_rn(o00*sc, o01*sc);
                *(__half2*)(C + (size_t)(r + 8) * DIM + c) = __floats2half2_rn(o10*sc, o11*sc);
            }
        }
    }
}

// ---------------------------------------------------------------------------
// attn_o: per (b,h), 256 t-rows/block, 8 warps x 32 rows (2 m-frags) each.
// (unchanged from round 6)
// ---------------------------------------------------------------------------
#define LDK 72

__global__ void __launch_bounds__(256,1) attn_o_fp16()
{
    __shared__ __half Ks[2][64*LDK];
    __shared__ __half Vs[2][64*LDK];

    const int tid  = threadIdx.x;
    const int lane = tid & 31, warp = tid >> 5;
    const int g = lane >> 2, t = lane & 3;
    const int t0 = blockIdx.x << 8;
    const int bh = blockIdx.y;
    const int b = bh >> 4, h = bh & 15;
    const size_t base = (size_t)b * SEQ * DIM + (size_t)h * HD;
    const __half* qb = g_qh + base;
    const __half* kb = g_kh + base;
    const __half* vb = g_vh + base;
    const int wr0 = t0 + (warp << 5);
    const int tile_t0 = (t0 >> 4) + (warp << 1);
    unsigned* ebw0 = g_expa + ((size_t)bh*(SEQ/16) + tile_t0    )*(SEQ/64)*512 + lane;
    unsigned* ebw1 = g_expa + ((size_t)bh*(SEQ/16) + tile_t0 + 1)*(SEQ/64)*512 + lane;

    unsigned qf[2][4][4];
    #pragma unroll
    for (int mf = 0; mf < 2; mf++) {
        const int r = wr0 + (mf << 4) + g;
        #pragma unroll
        for (int ks = 0; ks < 4; ks++) {
            const int c0 = (ks << 4) + (t << 1);
            qf[mf][ks][0] = *(const unsigned*)(qb + (size_t)r       * DIM + c0);
            qf[mf][ks][1] = *(const unsigned*)(qb + (size_t)(r + 8) * DIM + c0);
            qf[mf][ks][2] = *(const unsigned*)(qb + (size_t)r       * DIM + c0 + 8);
            qf[mf][ks][3] = *(const unsigned*)(qb + (size_t)(r + 8) * DIM + c0 + 8);
        }
    }

    float oacc[2][8][4];
    #pragma unroll
    for (int mf = 0; mf < 2; mf++)
        #pragma unroll
        for (int i = 0; i < 8; i++)
            #pragma unroll
            for (int v = 0; v < 4; v++) oacc[mf][i][v] = 0.f;
    float lp[2][2] = {{0.f,0.f},{0.f,0.f}};

    const unsigned ksb[2] = { (unsigned)__cvta_generic_to_shared(Ks[0]),
                              (unsigned)__cvta_generic_to_shared(Ks[1]) };
    const unsigned vsb[2] = { (unsigned)__cvta_generic_to_shared(Vs[0]),
                              (unsigned)__cvta_generic_to_shared(Vs[1]) };
    const int mi = lane >> 3, mj = lane & 7;

    const int r0c = tid >> 3,         c0c = (tid & 7) << 3;
    const int r1c = (tid + 256) >> 3, c1c = c0c;

    cpa16(ksb[0] + ((r0c*LDK + c0c) << 1), kb + (size_t)r0c * DIM + c0c);
    cpa16(ksb[0] + ((r1c*LDK + c1c) << 1), kb + (size_t)r1c * DIM + c1c);
    cpa16(vsb[0] + ((r0c*LDK + c0c) << 1), vb + (size_t)r0c * DIM + c0c);
    cpa16(vsb[0] + ((r1c*LDK + c1c) << 1), vb + (size_t)r1c * DIM + c1c);
    asm volatile("cp.async.commit_group;\n");

    for (int i = 0; i < SEQ/64; i++) {
        const int st = i & 1;
        if (i + 1 < SEQ/64) {
            const int ns = (i + 1) & 1;
            const size_t nb = (size_t)((i + 1) << 6) * DIM;
            cpa16(ksb[ns] + ((r0c*LDK + c0c) << 1), kb + nb + (size_t)r0c * DIM + c0c);
            cpa16(ksb[ns] + ((r1c*LDK + c1c) << 1), kb + nb + (size_t)r1c * DIM + c1c);
            cpa16(vsb[ns] + ((r0c*LDK + c0c) << 1), vb + nb + (size_t)r0c * DIM + c0c);
            cpa16(vsb[ns] + ((r1c*LDK + c1c) << 1), vb + nb + (size_t)r1c * DIM + c1c);
            asm volatile("cp.async.commit_group;\n");
            asm volatile("cp.async.wait_group 1;\n");
        } else {
            asm volatile("cp.async.wait_group 0;\n");
        }
        __syncthreads();

        const __half* ksp = Ks[st];
        unsigned* eb0 = ebw0 + (size_t)i * 512;
        unsigned* eb1 = ebw1 + (size_t)i * 512;

        #pragma unroll
        for (int ch = 0; ch < 2; ch++) {
            float sc[2][4][4];
            #pragma unroll
            for (int mf = 0; mf < 2; mf++)
                #pragma unroll
                for (int j = 0; j < 4; j++)
                    #pragma unroll
                    for (int v = 0; v < 4; v++) sc[mf][j][v] = 0.f;
            #pragma unroll
            for (int ks = 0; ks < 4; ks++) {
                const int kc = (ks << 4) + (t << 1);
                unsigned b0[4], b1[4];
                #pragma unroll
                for (int nt = 0; nt < 4; nt++) {
                    const int r = (ch << 5) + (nt << 3) + g;
                    b0[nt] = *(const unsigned*)&ksp[r*LDK + kc];
                    b1[nt] = *(const unsigned*)&ksp[r*LDK + kc + 8];
                }
                #pragma unroll
                for (int mf = 0; mf < 2; mf++)
                    #pragma unroll
                    for (int nt = 0; nt < 4; nt++)
                        mma16(sc[mf][nt], qf[mf][ks][0], qf[mf][ks][1],
                              qf[mf][ks][2], qf[mf][ks][3], b0[nt], b1[nt]);
            }

            unsigned ph[2][4][2];
            #pragma unroll
            for (int mf = 0; mf < 2; mf++) {
                unsigned* ebm = mf ? eb1 : eb0;
                #pragma unroll
                for (int nt = 0; nt < 4; nt++) {
                    float e0 = __expf(fminf(sc[mf][nt][0], 11.f));
                    float e1 = __expf(fminf(sc[mf][nt][1], 11.f));
                    float e2 = __expf(fminf(sc[mf][nt][2], 11.f));
                    float e3 = __expf(fminf(sc[mf][nt][3], 11.f));
                    lp[mf][0] += e0 + e1;
                    lp[mf][1] += e2 + e3;
                    ph[mf][nt][0] = h2u(__floats2half2_rn(e0, e1));
                    ph[mf][nt][1] = h2u(__floats2half2_rn(e2, e3));
                    const int w = (((ch << 2) + nt) << 1);
                    ebm[(w    ) << 5] = ph[mf][nt][0];
                    ebm[(w + 1) << 5] = ph[mf][nt][1];
                }
            }

            #pragma unroll
            for (int ks2 = 0; ks2 < 2; ks2++) {
                #pragma unroll
                for (int p = 0; p < 4; p++) {
                    const int vrow = (ch << 5) + (ks2 << 4) + ((mi & 1) << 3) + mj;
                    const int vcol = (p << 4) + ((mi >> 1) << 3);
                    unsigned r[4];
                    ldmx4t(r, vsb[st] + (unsigned)((vrow*LDK + vcol) << 1));
                    #pragma unroll
                    for (int mf = 0; mf < 2; mf++) {
                        mma16(oacc[mf][2*p],   ph[mf][2*ks2][0], ph[mf][2*ks2][1],
                              ph[mf][2*ks2+1][0], ph[mf][2*ks2+1][1], r[0], r[1]);
                        mma16(oacc[mf][2*p+1], ph[mf][2*ks2][0], ph[mf][2*ks2][1],
                              ph[mf][2*ks2+1][0], ph[mf][2*ks2+1][1], r[2], r[3]);
                    }
                }
            }
        }
        __syncthreads();
    }

    #pragma unroll
    for (int mf = 0; mf < 2; mf++) {
        float l0 = lp[mf][0], l1 = lp[mf][1];
        l0 += __shfl_xor_sync(0xffffffffu, l0, 1);
        l0 += __shfl_xor_sync(0xffffffffu, l0, 2);
        l1 += __shfl_xor_sync(0xffffffffu, l1, 1);
        l1 += __shfl_xor_sync(0xffffffffu, l1, 2);
        const float rl0 = 1.0f / l0;
        const float rl1 = 1.0f / l1;
        const int row0 = wr0 + (mf << 4) + g;
        if (t == 0) {
            g_rl[(size_t)bh * SEQ + row0]     = rl0;
            g_rl[(size_t)bh * SEQ + row0 + 8] = rl1;
        }
        #pragma unroll
        for (int nt = 0; nt < 8; nt++) {
            const int c = h*HD + (nt << 3) + (t << 1);
            *(__half2*)(g_ohh + (size_t)(b*SEQ + row0)     * DIM + c) =
                __floats2half2_rn(oacc[mf][nt][0]*rl0, oacc[mf][nt][1]*rl0);
            *(__half2*)(g_ohh + (size_t)(b*SEQ + row0 + 8) * DIM + c) =
                __floats2half2_rn(oacc[mf][nt][2]*rl1, oacc[mf][nt][3]*rl1);
        }
    }
}

// ---------------------------------------------------------------------------
// head_reduce (unchanged from round 6)
// ---------------------------------------------------------------------------
__global__ void __launch_bounds__(256) head_reduce(float* __restrict__ wout)
{
    __shared__ float tr[8][16][66];
    const int lane = threadIdx.x & 31, warp = threadIdx.x >> 5;
    const int blk = blockIdx.x;
    const int b = blk >> 7, tile_t = blk & 127;
    const int r0 = lane >> 2;
    const float invH = 1.0f / (float)HEADS;

    for (int ts = warp; ts < SEQ/64; ts += 8) {
        float2 acc[16];
        #pragma unroll
        for (int w = 0; w < 16; w++) acc[w] = make_float2(0.f, 0.f);

        for (int h = 0; h < HEADS; h++) {
            const int bh = b * HEADS + h;
            const unsigned* tb = g_expa +
                (((size_t)bh*(SEQ/16) + tile_t)*(SEQ/64) + ts)*512 + lane;
            const float rl0 = __ldg(&g_rl[(size_t)bh*SEQ + (tile_t<<4) + r0]);
            const float rl1 = __ldg(&g_rl[(size_t)bh*SEQ + (tile_t<<4) + r0 + 8]);
            #pragma unroll
            for (int w = 0; w < 16; w++) {
                unsigned u = __ldg(tb + (w << 5));
                float2 f = __half22float2(*(__half2*)&u);
                const float rl = (w & 1) ? rl1 : rl0;
                acc[w].x += f.x * rl;
                acc[w].y += f.y * rl;
            }
        }

        #pragma unroll
        for (int w = 0; w < 16; w++) {
            const int r = r0 + ((w & 1) << 3);
            const int c = ((w >> 1) << 3) + ((lane & 3) << 1);
            tr[warp][r][c]     = acc[w].x * invH;
            tr[warp][r][c + 1] = acc[w].y * invH;
        }
        __syncwarp();
        #pragma unroll
        for (int r = 0; r < 16; r++) {
            float2 v = *(float2*)&tr[warp][r][lane << 1];
            *(float2*)(wout + ((size_t)b*SEQ + (tile_t<<4) + r)*SEQ + (ts<<6) + (lane<<1)) = v;
        }
        __syncwarp();
    }
}

// ---------------------------------------------------------------------------
extern "C" void kernel_launch(void* const* d_in, const int* in_sizes, int n_in,
                              void* d_out, int out_size)
{
    const float* Q  = (const float*)d_in[0];
    const float* K  = (const float*)d_in[1];
    const float* V  = (const float*)d_in[2];
    const float* Wq = (const float*)d_in[3];
    const float* bq = (const float*)d_in[4];
    const float* Wk = (const float*)d_in[5];
    const float* bk = (const float*)d_in[6];
    const float* Wv = (const float*)d_in[7];
    const float* bv = (const float*)d_in[8];
    const float* Wo = (const float*)d_in[9];
    const float* bo = (const float*)d_in[10];

    float* outO = (float*)d_out;                       // [B,T,D]
    float* outW = outO + (size_t)BATCH * SEQ * DIM;    // [B,T,T]

    __half *pin, *pw, *pq, *pk, *pv, *poh;
    cudaGetSymbolAddress((void**)&pin, g_in);
    cudaGetSymbolAddress((void**)&pw,  g_w);
    cudaGetSymbolAddress((void**)&pq,  g_qh);
    cudaGetSymbolAddress((void**)&pk,  g_kh);
    cudaGetSymbolAddress((void**)&pv,  g_vh);
    cudaGetSymbolAddress((void**)&poh, g_ohh);

    const int nIn4 = MTOT*DIM/4, nW4 = DIM*DIM/4;
    cvt_f2h<<<512, 256>>>(Q,  pin,              nIn4);
    cvt_f2h<<<512, 256>>>(K,  pin +   MTOT*DIM, nIn4);
    cvt_f2h<<<512, 256>>>(V,  pin + 2*MTOT*DIM, nIn4);
    cvt_f2h<<<256, 256>>>(Wq, pw,               nW4);
    cvt_f2h<<<256, 256>>>(Wk, pw +   DIM*DIM,   nW4);
    cvt_f2h<<<256, 256>>>(Wv, pw + 2*DIM*DIM,   nW4);
    cvt_f2h<<<256, 256>>>(Wo, pw + 3*DIM*DIM,   nW4);

    dim3 pg(DIM/128, MTOT/128);        // (8, 64)
    gemm_hh<2><<<pg, 256>>>(pin,              pw,             bq, pq);
    gemm_hh<1><<<pg, 256>>>(pin +   MTOT*DIM, pw +   DIM*DIM, bk, pk);
    gemm_hh<1><<<pg, 256>>>(pin + 2*MTOT*DIM, pw + 2*DIM*DIM, bv, pv);

    attn_o_fp16<<<dim3(SEQ/256, BATCH*HEADS), 256>>>();
    head_reduce<<<BATCH*(SEQ/16), 256>>>(outW);

    gemm_hh<0><<<pg, 256>>>(poh, pw + 3*DIM*DIM, bo, outO);
}

// round 9
// speedup vs baseline: 1.1269x; 1.1269x over previous
#include <cuda_runtime.h>
#include <cuda_fp16.h>
#include <cstdint>
#include <math.h>

#define BATCH 4
#define SEQ   2048
#define DIM   1024
#define HEADS 16
#define HD    64
#define MTOT  (BATCH*SEQ)   // 8192

// Scratch (allocation-free rule: __device__ globals)
__device__ __half g_in [3][MTOT*DIM];     // fp16 copies of Q,K,V inputs
__device__ __half g_w  [4][DIM*DIM];      // fp16 copies of Wq,Wk,Wv,Wo
__device__ __half g_qh [MTOT*DIM];        // projected q (pre-scaled 0.125)
__device__ __half g_kh [MTOT*DIM];
__device__ __half g_vh [MTOT*DIM];
__device__ __half g_ohh[MTOT*DIM];        // attention output heads
__device__ float  g_rl [BATCH*HEADS*SEQ];
// exp(scores), FRAGMENT-BLOCKED: tile (bh,tile_t,tile_s) of 16x64 halves
// = 512 words; word addr = tile*512 + word_idx*32 + lane.
__device__ unsigned g_expa[(size_t)BATCH*HEADS*(SEQ/16)*(SEQ/64)*512];

// ---------------------------------------------------------------------------
// helpers
// ---------------------------------------------------------------------------
__device__ __forceinline__ void mma16(float c[4],
    unsigned a0, unsigned a1, unsigned a2, unsigned a3,
    unsigned b0, unsigned b1)
{
    asm volatile(
      "mma.sync.aligned.m16n8k16.row.col.f32.f16.f16.f32 "
      "{%0,%1,%2,%3},{%4,%5,%6,%7},{%8,%9},{%0,%1,%2,%3};"
      : "+f"(c[0]), "+f"(c[1]), "+f"(c[2]), "+f"(c[3])
      : "r"(a0), "r"(a1), "r"(a2), "r"(a3), "r"(b0), "r"(b1));
}
__device__ __forceinline__ void ldmx4(unsigned r[4], unsigned addr)
{
    asm volatile(
      "ldmatrix.sync.aligned.m8n8.x4.shared.b16 {%0,%1,%2,%3}, [%4];"
      : "=r"(r[0]), "=r"(r[1]), "=r"(r[2]), "=r"(r[3]) : "r"(addr));
}
__device__ __forceinline__ void ldmx4t(unsigned r[4], unsigned addr)
{
    asm volatile(
      "ldmatrix.sync.aligned.m8n8.x4.trans.shared.b16 {%0,%1,%2,%3}, [%4];"
      : "=r"(r[0]), "=r"(r[1]), "=r"(r[2]), "=r"(r[3]) : "r"(addr));
}
__device__ __forceinline__ unsigned h2u(__half2 h) { return *(unsigned*)&h; }
__device__ __forceinline__ void cpa16(unsigned dst, const void* src) {
    asm volatile("cp.async.cg.shared.global [%0], [%1], 16;\n" :: "r"(dst), "l"(src));
}
__device__ __forceinline__ uint32_t smem_u32(const void* p) {
    uint32_t a;
    asm("{ .reg .u64 t; cvta.to.shared.u64 t, %1; cvt.u32.u64 %0, t; }"
        : "=r"(a) : "l"(p));
    return a;
}

// ---------------------------------------------------------------------------
// single fp32->fp16 convert covering all 7 tensors (grid.y selects)
// ---------------------------------------------------------------------------
__global__ void __launch_bounds__(256) cvt_all(
    const float* q, const float* k, const float* v,
    const float* wq, const float* wk, const float* wv, const float* wo)
{
    const int y = blockIdx.y;
    const float* src;
    __half* dst;
    int n4;
    switch (y) {
        case 0: src = q;  dst = g_in[0]; n4 = MTOT*DIM/4; break;
        case 1: src = k;  dst = g_in[1]; n4 = MTOT*DIM/4; break;
        case 2: src = v;  dst = g_in[2]; n4 = MTOT*DIM/4; break;
        case 3: src = wq; dst = g_w[0];  n4 = DIM*DIM/4;  break;
        case 4: src = wk; dst = g_w[1];  n4 = DIM*DIM/4;  break;
        case 5: src = wv; dst = g_w[2];  n4 = DIM*DIM/4;  break;
        default: src = wo; dst = g_w[3]; n4 = DIM*DIM/4;  break;
    }
    for (int i = blockIdx.x*256 + threadIdx.x; i < n4; i += gridDim.x*256) {
        float4 f = *(const float4*)(src + (size_t)i*4);
        *(__half2*)(dst + (size_t)i*4)     = __floats2half2_rn(f.x, f.y);
        *(__half2*)(dst + (size_t)i*4 + 2) = __floats2half2_rn(f.z, f.w);
    }
}

// ---------------------------------------------------------------------------
// fp16 NT GEMM (mma.sync + ldmatrix fragments): C = A*W^T + bias
// Block 128x128, BK=32, 256 threads, 2-stage cp.async, warp tile 64x32.
// OMODE: 0 fp32-out, 1 fp16-out, 2 fp16-out scaled 0.125.
// ---------------------------------------------------------------------------
#define LDH 40
template<int OMODE>
__global__ void __launch_bounds__(256,2) gemm_hh(
    const __half* __restrict__ A, const __half* __restrict__ W,
    const float* __restrict__ bias, void* __restrict__ Cv)
{
    __shared__ __half As[2][128*LDH];
    __shared__ __half Ws[2][128*LDH];
    const int tid  = threadIdx.x;
    const int lane = tid & 31, warp = tid >> 5;
    const int g = lane >> 2, t = lane & 3;
    const int m0 = blockIdx.y << 7, n0 = blockIdx.x << 7;
    const int wm = (warp >> 2) << 6, wn = (warp & 3) << 5;
    const __half* Ab = A + (size_t)m0 * DIM;
    const __half* Wb = W + (size_t)n0 * DIM;

    // cp.async coords: 512 16B-chunks per operand per stage, 2 per thread
    const int ch0 = tid << 1, ch1 = ch0 + 1;
    const int r0 = ch0 >> 2, c0 = (ch0 & 3) << 3;
    const int r1 = ch1 >> 2, c1 = (ch1 & 3) << 3;
    const unsigned asb[2] = { smem_u32(As[0]), smem_u32(As[1]) };
    const unsigned wsb[2] = { smem_u32(Ws[0]), smem_u32(Ws[1]) };

    // ldmatrix lane-address components
    const int aRow = wm + (lane & 15);                 // + mt*16
    const int aKof = (lane >> 4) << 3;                 // + s*16
    const int bRow = wn + ((lane >> 4) << 3) + (lane & 7);   // + p*16
    const int bKof = ((lane >> 3) & 1) << 3;           // + s*16

    float acc[4][4][4];
    #pragma unroll
    for (int i = 0; i < 4; i++)
        #pragma unroll
        for (int j = 0; j < 4; j++)
            #pragma unroll
            for (int v = 0; v < 4; v++) acc[i][j][v] = 0.f;

    // prologue: k-tile 0 -> stage 0
    cpa16(asb[0] + ((r0*LDH + c0) << 1), Ab + (size_t)r0 * DIM + c0);
    cpa16(asb[0] + ((r1*LDH + c1) << 1), Ab + (size_t)r1 * DIM + c1);
    cpa16(wsb[0] + ((r0*LDH + c0) << 1), Wb + (size_t)r0 * DIM + c0);
    cpa16(wsb[0] + ((r1*LDH + c1) << 1), Wb + (size_t)r1 * DIM + c1);
    asm volatile("cp.async.commit_group;\n");

    for (int kt = 0; kt < DIM/32; kt++) {
        const int st = kt & 1;
        if (kt + 1 < DIM/32) {
            const int ns = (kt + 1) & 1;
            const int k0 = (kt + 1) << 5;
            cpa16(asb[ns] + ((r0*LDH + c0) << 1), Ab + (size_t)r0 * DIM + k0 + c0);
            cpa16(asb[ns] + ((r1*LDH + c1) << 1), Ab + (size_t)r1 * DIM + k0 + c1);
            cpa16(wsb[ns] + ((r0*LDH + c0) << 1), Wb + (size_t)r0 * DIM + k0 + c0);
            cpa16(wsb[ns] + ((r1*LDH + c1) << 1), Wb + (size_t)r1 * DIM + k0 + c1);
            asm volatile("cp.async.commit_group;\n");
            asm volatile("cp.async.wait_group 1;\n");
        } else {
            asm volatile("cp.async.wait_group 0;\n");
        }
        __syncthreads();

        #pragma unroll
        for (int s = 0; s < 2; s++) {
            const int kh = s << 4;
            unsigned af[4][4], bf[4][2];
            #pragma unroll
            for (int mt = 0; mt < 4; mt++)
                ldmx4(af[mt], asb[st] +
                      (unsigned)(((aRow + (mt << 4))*LDH + kh + aKof) << 1));
            #pragma unroll
            for (int p = 0; p < 2; p++) {
                unsigned bx[4];
                ldmx4(bx, wsb[st] +
                      (unsigned)(((bRow + (p << 4))*LDH + kh + bKof) << 1));
                bf[2*p][0]   = bx[0]; bf[2*p][1]   = bx[1];
                bf[2*p+1][0] = bx[2]; bf[2*p+1][1] = bx[3];
            }
            #pragma unroll
            for (int mt = 0; mt < 4; mt++)
                #pragma unroll
                for (int nt = 0; nt < 4; nt++)
                    mma16(acc[mt][nt], af[mt][0], af[mt][1], af[mt][2], af[mt][3],
                          bf[nt][0], bf[nt][1]);
        }
        __syncthreads();
    }

    #pragma unroll
    for (int mt = 0; mt < 4; mt++) {
        int r = m0 + wm + (mt << 4) + g;
        #pragma unroll
        for (int nt = 0; nt < 4; nt++) {
            int c = n0 + wn + (nt << 3) + (t << 1);
            float2 bv = *(const float2*)(bias + c);
            float o00 = acc[mt][nt][0] + bv.x, o01 = acc[mt][nt][1] + bv.y;
            float o10 = acc[mt][nt][2] + bv.x, o11 = acc[mt][nt][3] + bv.y;
            if (OMODE == 0) {
                float* C = (float*)Cv;
                *(float2*)(C + (size_t)r       * DIM + c) = make_float2(o00, o01);
                *(float2*)(C + (size_t)(r + 8) * DIM + c) = make_float2(o10, o11);
            } else {
                const float sc = (OMODE == 2) ? 0.125f : 1.0f;
                __half* C = (__half*)Cv;
                *(__half2*)(C + (size_t)r       * DIM + c) = __floats2half2_rn(o00*sc, o01*sc);
                *(__half2*)(C + (size_t)(r + 8) * DIM + c) = __floats2half2_rn(o10*sc, o11*sc);
            }
        }
    }
}

// ---------------------------------------------------------------------------
// attn_o (unchanged from round 6/7)
// ---------------------------------------------------------------------------
#define LDK 72

__global__ void __launch_bounds__(256,1) attn_o_fp16()
{
    __shared__ __half Ks[2][64*LDK];
    __shared__ __half Vs[2][64*LDK];

    const int tid  = threadIdx.x;
    const int lane = tid & 31, warp = tid >> 5;
    const int g = lane >> 2, t = lane & 3;
    const int t0 = blockIdx.x << 8;
    const int bh = blockIdx.y;
    const int b = bh >> 4, h = bh & 15;
    const size_t base = (size_t)b * SEQ * DIM + (size_t)h * HD;
    const __half* qb = g_qh + base;
    const __half* kb = g_kh + base;
    const __half* vb = g_vh + base;
    const int wr0 = t0 + (warp << 5);
    const int tile_t0 = (t0 >> 4) + (warp << 1);
    unsigned* ebw0 = g_expa + ((size_t)bh*(SEQ/16) + tile_t0    )*(SEQ/64)*512 + lane;
    unsigned* ebw1 = g_expa + ((size_t)bh*(SEQ/16) + tile_t0 + 1)*(SEQ/64)*512 + lane;

    unsigned qf[2][4][4];
    #pragma unroll
    for (int mf = 0; mf < 2; mf++) {
        const int r = wr0 + (mf << 4) + g;
        #pragma unroll
        for (int ks = 0; ks < 4; ks++) {
            const int c0 = (ks << 4) + (t << 1);
            qf[mf][ks][0] = *(const unsigned*)(qb + (size_t)r       * DIM + c0);
            qf[mf][ks][1] = *(const unsigned*)(qb + (size_t)(r + 8) * DIM + c0);
            qf[mf][ks][2] = *(const unsigned*)(qb + (size_t)r       * DIM + c0 + 8);
            qf[mf][ks][3] = *(const unsigned*)(qb + (size_t)(r + 8) * DIM + c0 + 8);
        }
    }

    float oacc[2][8][4];
    #pragma unroll
    for (int mf = 0; mf < 2; mf++)
        #pragma unroll
        for (int i = 0; i < 8; i++)
            #pragma unroll
            for (int v = 0; v < 4; v++) oacc[mf][i][v] = 0.f;
    float lp[2][2] = {{0.f,0.f},{0.f,0.f}};

    const unsigned ksb[2] = { smem_u32(Ks[0]), smem_u32(Ks[1]) };
    const unsigned vsb[2] = { smem_u32(Vs[0]), smem_u32(Vs[1]) };
    const int mi = lane >> 3, mj = lane & 7;

    const int r0c = tid >> 3,         c0c = (tid & 7) << 3;
    const int r1c = (tid + 256) >> 3, c1c = c0c;

    cpa16(ksb[0] + ((r0c*LDK + c0c) << 1), kb + (size_t)r0c * DIM + c0c);
    cpa16(ksb[0] + ((r1c*LDK + c1c) << 1), kb + (size_t)r1c * DIM + c1c);
    cpa16(vsb[0] + ((r0c*LDK + c0c) << 1), vb + (size_t)r0c * DIM + c0c);
    cpa16(vsb[0] + ((r1c*LDK + c1c) << 1), vb + (size_t)r1c * DIM + c1c);
    asm volatile("cp.async.commit_group;\n");

    for (int i = 0; i < SEQ/64; i++) {
        const int st = i & 1;
        if (i + 1 < SEQ/64) {
            const int ns = (i + 1) & 1;
            const size_t nb = (size_t)((i + 1) << 6) * DIM;
            cpa16(ksb[ns] + ((r0c*LDK + c0c) << 1), kb + nb + (size_t)r0c * DIM + c0c);
            cpa16(ksb[ns] + ((r1c*LDK + c1c) << 1), kb + nb + (size_t)r1c * DIM + c1c);
            cpa16(vsb[ns] + ((r0c*LDK + c0c) << 1), vb + nb + (size_t)r0c * DIM + c0c);
            cpa16(vsb[ns] + ((r1c*LDK + c1c) << 1), vb + nb + (size_t)r1c * DIM + c1c);
            asm volatile("cp.async.commit_group;\n");
            asm volatile("cp.async.wait_group 1;\n");
        } else {
            asm volatile("cp.async.wait_group 0;\n");
        }
        __syncthreads();

        const __half* ksp = Ks[st];
        unsigned* eb0 = ebw0 + (size_t)i * 512;
        unsigned* eb1 = ebw1 + (size_t)i * 512;

        #pragma unroll
        for (int ch = 0; ch < 2; ch++) {
            float sc[2][4][4];
            #pragma unroll
            for (int mf = 0; mf < 2; mf++)
                #pragma unroll
                for (int j = 0; j < 4; j++)
                    #pragma unroll
                    for (int v = 0; v < 4; v++) sc[mf][j][v] = 0.f;
            #pragma unroll
            for (int ks = 0; ks < 4; ks++) {
                const int kc = (ks << 4) + (t << 1);
                unsigned b0[4], b1[4];
                #pragma unroll
                for (int nt = 0; nt < 4; nt++) {
                    const int r = (ch << 5) + (nt << 3) + g;
                    b0[nt] = *(const unsigned*)&ksp[r*LDK + kc];
                    b1[nt] = *(const unsigned*)&ksp[r*LDK + kc + 8];
                }
                #pragma unroll
                for (int mf = 0; mf < 2; mf++)
                    #pragma unroll
                    for (int nt = 0; nt < 4; nt++)
                        mma16(sc[mf][nt], qf[mf][ks][0], qf[mf][ks][1],
                              qf[mf][ks][2], qf[mf][ks][3], b0[nt], b1[nt]);
            }

            unsigned ph[2][4][2];
            #pragma unroll
            for (int mf = 0; mf < 2; mf++) {
                unsigned* ebm = mf ? eb1 : eb0;
                #pragma unroll
                for (int nt = 0; nt < 4; nt++) {
                    float e0 = __expf(fminf(sc[mf][nt][0], 11.f));
                    float e1 = __expf(fminf(sc[mf][nt][1], 11.f));
                    float e2 = __expf(fminf(sc[mf][nt][2], 11.f));
                    float e3 = __expf(fminf(sc[mf][nt][3], 11.f));
                    lp[mf][0] += e0 + e1;
                    lp[mf][1] += e2 + e3;
                    ph[mf][nt][0] = h2u(__floats2half2_rn(e0, e1));
                    ph[mf][nt][1] = h2u(__floats2half2_rn(e2, e3));
                    const int w = (((ch << 2) + nt) << 1);
                    ebm[(w    ) << 5] = ph[mf][nt][0];
                    ebm[(w + 1) << 5] = ph[mf][nt][1];
                }
            }

            #pragma unroll
            for (int ks2 = 0; ks2 < 2; ks2++) {
                #pragma unroll
                for (int p = 0; p < 4; p++) {
                    const int vrow = (ch << 5) + (ks2 << 4) + ((mi & 1) << 3) + mj;
                    const int vcol = (p << 4) + ((mi >> 1) << 3);
                    unsigned r[4];
                    ldmx4t(r, vsb[st] + (unsigned)((vrow*LDK + vcol) << 1));
                    #pragma unroll
                    for (int mf = 0; mf < 2; mf++) {
                        mma16(oacc[mf][2*p],   ph[mf][2*ks2][0], ph[mf][2*ks2][1],
                              ph[mf][2*ks2+1][0], ph[mf][2*ks2+1][1], r[0], r[1]);
                        mma16(oacc[mf][2*p+1], ph[mf][2*ks2][0], ph[mf][2*ks2][1],
                              ph[mf][2*ks2+1][0], ph[mf][2*ks2+1][1], r[2], r[3]);
                    }
                }
            }
        }
        __syncthreads();
    }

    #pragma unroll
    for (int mf = 0; mf < 2; mf++) {
        float l0 = lp[mf][0], l1 = lp[mf][1];
        l0 += __shfl_xor_sync(0xffffffffu, l0, 1);
        l0 += __shfl_xor_sync(0xffffffffu, l0, 2);
        l1 += __shfl_xor_sync(0xffffffffu, l1, 1);
        l1 += __shfl_xor_sync(0xffffffffu, l1, 2);
        const float rl0 = 1.0f / l0;
        const float rl1 = 1.0f / l1;
        const int row0 = wr0 + (mf << 4) + g;
        if (t == 0) {
            g_rl[(size_t)bh * SEQ + row0]     = rl0;
            g_rl[(size_t)bh * SEQ + row0 + 8] = rl1;
        }
        #pragma unroll
        for (int nt = 0; nt < 8; nt++) {
            const int c = h*HD + (nt << 3) + (t << 1);
            *(__half2*)(g_ohh + (size_t)(b*SEQ + row0)     * DIM + c) =
                __floats2half2_rn(oacc[mf][nt][0]*rl0, oacc[mf][nt][1]*rl0);
            *(__half2*)(g_ohh + (size_t)(b*SEQ + row0 + 8) * DIM + c) =
                __floats2half2_rn(oacc[mf][nt][2]*rl1, oacc[mf][nt][3]*rl1);
        }
    }
}

// ---------------------------------------------------------------------------
// head_reduce v2: uint4 (LDG.128) loads of the fragment-blocked expa.
// Thread lane holds ONE fixed row r=(lane&7)+8*((lane>>3)&1); its uint4 at
// word offset 4*lane+128k covers cols 8*(lane>>4)+16k+2j (j=0..3).
// ---------------------------------------------------------------------------
__global__ void __launch_bounds__(256) head_reduce(float* __restrict__ wout)
{
    __shared__ float tr[8][16][66];
    const int lane = threadIdx.x & 31, warp = threadIdx.x >> 5;
    const int blk = blockIdx.x;
    const int b = blk >> 7, tile_t = blk & 127;
    const int r = (lane & 7) + (((lane >> 3) & 1) << 3);
    const int cbase = (lane >> 4) << 3;
    const float invH = 1.0f / (float)HEADS;

    for (int ts = warp; ts < SEQ/64; ts += 8) {
        float2 acc[4][4];
        #pragma unroll
        for (int k = 0; k < 4; k++)
            #pragma unroll
            for (int j = 0; j < 4; j++) acc[k][j] = make_float2(0.f, 0.f);

        for (int h = 0; h < HEADS; h++) {
            const int bh = b * HEADS + h;
            const size_t tb4 = ((((size_t)bh*(SEQ/16) + tile_t)*(SEQ/64) + ts)*512) >> 2;
            const uint4* p = (const uint4*)g_expa + tb4 + lane;
            const float rl = __ldg(&g_rl[(size_t)bh*SEQ + (tile_t << 4) + r]);
            #pragma unroll
            for (int k = 0; k < 4; k++) {
                uint4 u = __ldg(p + (k << 5));
                float2 f0 = __half22float2(*(__half2*)&u.x);
                float2 f1 = __half22float2(*(__half2*)&u.y);
                float2 f2 = __half22float2(*(__half2*)&u.z);
                float2 f3 = __half22float2(*(__half2*)&u.w);
                acc[k][0].x += f0.x*rl; acc[k][0].y += f0.y*rl;
                acc[k][1].x += f1.x*rl; acc[k][1].y += f1.y*rl;
                acc[k][2].x += f2.x*rl; acc[k][2].y += f2.y*rl;
                acc[k][3].x += f3.x*rl; acc[k][3].y += f3.y*rl;
            }
        }

        // transpose via smem (row fixed per lane; cols = cbase+16k+2j)
        #pragma unroll
        for (int k = 0; k < 4; k++)
            #pragma unroll
            for (int j = 0; j < 4; j++) {
                const int c = cbase + (k << 4) + (j << 1);
                tr[warp][r][c]     = acc[k][j].x * invH;
                tr[warp][r][c + 1] = acc[k][j].y * invH;
            }
        __syncwarp();
        #pragma unroll
        for (int rr = 0; rr < 16; rr++) {
            float2 v = *(float2*)&tr[warp][rr][lane << 1];
            *(float2*)(wout + ((size_t)b*SEQ + (tile_t<<4) + rr)*SEQ + (ts<<6) + (lane<<1)) = v;
        }
        __syncwarp();
    }
}

// ---------------------------------------------------------------------------
extern "C" void kernel_launch(void* const* d_in, const int* in_sizes, int n_in,
                              void* d_out, int out_size)
{
    const float* Q  = (const float*)d_in[0];
    const float* K  = (const float*)d_in[1];
    const float* V  = (const float*)d_in[2];
    const float* Wq = (const float*)d_in[3];
    const float* bq = (const float*)d_in[4];
    const float* Wk = (const float*)d_in[5];
    const float* bk = (const float*)d_in[6];
    const float* Wv = (const float*)d_in[7];
    const float* bv = (const float*)d_in[8];
    const float* Wo = (const float*)d_in[9];
    const float* bo = (const float*)d_in[10];

    float* outO = (float*)d_out;                       // [B,T,D]
    float* outW = outO + (size_t)BATCH * SEQ * DIM;    // [B,T,T]

    __half *pin, *pw, *pq, *pk, *pv, *poh;
    cudaGetSymbolAddress((void**)&pin, g_in);
    cudaGetSymbolAddress((void**)&pw,  g_w);
    cudaGetSymbolAddress((void**)&pq,  g_qh);
    cudaGetSymbolAddress((void**)&pk,  g_kh);
    cudaGetSymbolAddress((void**)&pv,  g_vh);
    cudaGetSymbolAddress((void**)&poh, g_ohh);

    cvt_all<<<dim3(256, 7), 256>>>(Q, K, V, Wq, Wk, Wv, Wo);

    dim3 pg(DIM/128, MTOT/128);        // (8, 64)
    gemm_hh<2><<<pg, 256>>>(pin,              pw,             bq, pq);
    gemm_hh<1><<<pg, 256>>>(pin +   MTOT*DIM, pw +   DIM*DIM, bk, pk);
    gemm_hh<1><<<pg, 256>>>(pin + 2*MTOT*DIM, pw + 2*DIM*DIM, bv, pv);

    attn_o_fp16<<<dim3(SEQ/256, BATCH*HEADS), 256>>>();

    // Wo-GEMM at launch index 5 so ncu (-s 5 -c 1) profiles the GEMM
    gemm_hh<0><<<pg, 256>>>(poh, pw + 3*DIM*DIM, bo, outO);

    head_reduce<<<BATCH*(SEQ/16), 256>>>(outW);
}

// round 12
// speedup vs baseline: 1.1328x; 1.0052x over previous
#include <cuda_runtime.h>
#include <cuda_fp16.h>
#include <cstdint>
#include <math.h>

#define BATCH 4
#define SEQ   2048
#define DIM   1024
#define HEADS 16
#define HD    64
#define MTOT  (BATCH*SEQ)   // 8192

// Scratch (allocation-free rule: __device__ globals)
__device__ __half g_in [3][MTOT*DIM];     // fp16 copies of Q,K,V inputs
__device__ __half g_w  [4][DIM*DIM];      // fp16 copies of Wq,Wk,Wv,Wo
__device__ __half g_qh [MTOT*DIM];        // projected q (pre-scaled 0.125)
__device__ __half g_kh [MTOT*DIM];
__device__ __half g_vh [MTOT*DIM];
__device__ __half g_ohh[MTOT*DIM];        // attention output heads
__device__ float  g_rl [BATCH*HEADS*SEQ];
// exp(scores), FRAGMENT-BLOCKED: tile (bh,tile_t,tile_s) of 16x64 halves
// = 512 words; word addr = tile*512 + word_idx*32 + lane.
__device__ unsigned g_expa[(size_t)BATCH*HEADS*(SEQ/16)*(SEQ/64)*512];

// ---------------------------------------------------------------------------
// helpers
// ---------------------------------------------------------------------------
__device__ __forceinline__ void mma16(float c[4],
    unsigned a0, unsigned a1, unsigned a2, unsigned a3,
    unsigned b0, unsigned b1)
{
    asm volatile(
      "mma.sync.aligned.m16n8k16.row.col.f32.f16.f16.f32 "
      "{%0,%1,%2,%3},{%4,%5,%6,%7},{%8,%9},{%0,%1,%2,%3};"
      : "+f"(c[0]), "+f"(c[1]), "+f"(c[2]), "+f"(c[3])
      : "r"(a0), "r"(a1), "r"(a2), "r"(a3), "r"(b0), "r"(b1));
}
__device__ __forceinline__ void ldmx4(unsigned r[4], unsigned addr)
{
    asm volatile(
      "ldmatrix.sync.aligned.m8n8.x4.shared.b16 {%0,%1,%2,%3}, [%4];"
      : "=r"(r[0]), "=r"(r[1]), "=r"(r[2]), "=r"(r[3]) : "r"(addr));
}
__device__ __forceinline__ void ldmx4t(unsigned r[4], unsigned addr)
{
    asm volatile(
      "ldmatrix.sync.aligned.m8n8.x4.trans.shared.b16 {%0,%1,%2,%3}, [%4];"
      : "=r"(r[0]), "=r"(r[1]), "=r"(r[2]), "=r"(r[3]) : "r"(addr));
}
__device__ __forceinline__ unsigned h2u(__half2 h) { return *(unsigned*)&h; }
__device__ __forceinline__ void cpa16(unsigned dst, const void* src) {
    asm volatile("cp.async.cg.shared.global [%0], [%1], 16;\n" :: "r"(dst), "l"(src));
}
__device__ __forceinline__ uint32_t smem_u32(const void* p) {
    uint32_t a;
    asm("{ .reg .u64 t; cvta.to.shared.u64 t, %1; cvt.u32.u64 %0, t; }"
        : "=r"(a) : "l"(p));
    return a;
}

// ---------------------------------------------------------------------------
// single fp32->fp16 convert covering all 7 tensors (grid.y selects)
// ---------------------------------------------------------------------------
__global__ void __launch_bounds__(256) cvt_all(
    const float* q, const float* k, const float* v,
    const float* wq, const float* wk, const float* wv, const float* wo)
{
    const int y = blockIdx.y;
    const float* src;
    __half* dst;
    int n4;
    switch (y) {
        case 0: src = q;  dst = g_in[0]; n4 = MTOT*DIM/4; break;
        case 1: src = k;  dst = g_in[1]; n4 = MTOT*DIM/4; break;
        case 2: src = v;  dst = g_in[2]; n4 = MTOT*DIM/4; break;
        case 3: src = wq; dst = g_w[0];  n4 = DIM*DIM/4;  break;
        case 4: src = wk; dst = g_w[1];  n4 = DIM*DIM/4;  break;
        case 5: src = wv; dst = g_w[2];  n4 = DIM*DIM/4;  break;
        default: src = wo; dst = g_w[3]; n4 = DIM*DIM/4;  break;
    }
    for (int i = blockIdx.x*256 + threadIdx.x; i < n4; i += gridDim.x*256) {
        float4 f = *(const float4*)(src + (size_t)i*4);
        *(__half2*)(dst + (size_t)i*4)     = __floats2half2_rn(f.x, f.y);
        *(__half2*)(dst + (size_t)i*4 + 2) = __floats2half2_rn(f.z, f.w);
    }
}

// ---------------------------------------------------------------------------
// fp16 NT GEMM, 4-stage cp.async pipeline, ONE barrier per k-tile.
// Block 128x128, BK=32, 256 threads, warp tile 64x32.
// OMODE: 0 fp32-out, 1 fp16-out, 2 fp16-out scaled 0.125.
// ---------------------------------------------------------------------------
#define LDH   40
#define G_STB (128*LDH)                 // halves per stage-operand (10240 B)
#define G_SMEM_BYTES (4 * 2 * G_STB * 2)  // 81920

template<int OMODE>
__global__ void __launch_bounds__(256,2) gemm_hh(
    const __half* __restrict__ A, const __half* __restrict__ W,
    const float* __restrict__ bias, void* __restrict__ Cv)
{
    extern __shared__ __half smh[];
    const unsigned sb = smem_u32(smh);
    const int tid  = threadIdx.x;
    const int lane = tid & 31, warp = tid >> 5;
    const int g = lane >> 2, t = lane & 3;
    const int m0 = blockIdx.y << 7, n0 = blockIdx.x << 7;
    const int wm = (warp >> 2) << 6, wn = (warp & 3) << 5;
    const __half* Ab = A + (size_t)m0 * DIM;
    const __half* Wb = W + (size_t)n0 * DIM;

    // cp.async coords: 512 16B-chunks per operand per stage, 2 per thread
    const int ch0 = tid << 1, ch1 = ch0 + 1;
    const int r0 = ch0 >> 2, c0 = (ch0 & 3) << 3;
    const int r1 = ch1 >> 2, c1 = (ch1 & 3) << 3;
    const unsigned aOff0 = (unsigned)((r0*LDH + c0) << 1);
    const unsigned aOff1 = (unsigned)((r1*LDH + c1) << 1);

    // ldmatrix lane-address components
    const int aRow = wm + (lane & 15);                 // + mt*16
    const int aKof = (lane >> 4) << 3;                 // + s*16
    const int bRow = wn + ((lane >> 4) << 3) + (lane & 7);   // + p*16
    const int bKof = ((lane >> 3) & 1) << 3;           // + s*16

    float acc[4][4][4];
    #pragma unroll
    for (int i = 0; i < 4; i++)
        #pragma unroll
        for (int j = 0; j < 4; j++)
            #pragma unroll
            for (int v = 0; v < 4; v++) acc[i][j][v] = 0.f;

    // prologue: k-tiles 0..2 -> stages 0..2
    #pragma unroll
    for (int s = 0; s < 3; s++) {
        const unsigned stB = (unsigned)(s * 2 * G_STB) << 1;   // bytes
        const int k0 = s << 5;
        cpa16(sb + stB + aOff0,                    Ab + (size_t)r0 * DIM + k0 + c0);
        cpa16(sb + stB + aOff1,                    Ab + (size_t)r1 * DIM + k0 + c1);
        cpa16(sb + stB + (G_STB << 1) + aOff0,     Wb + (size_t)r0 * DIM + k0 + c0);
        cpa16(sb + stB + (G_STB << 1) + aOff1,     Wb + (size_t)r1 * DIM + k0 + c1);
        asm volatile("cp.async.commit_group;\n");
    }

    for (int kt = 0; kt < 32; kt++) {
        // stage kt must have arrived
        if (kt <= 29)      asm volatile("cp.async.wait_group 2;\n");
        else if (kt == 30) asm volatile("cp.async.wait_group 1;\n");
        else               asm volatile("cp.async.wait_group 0;\n");
        __syncthreads();

        // issue loads for k-tile kt+3 into buffer (kt+3)&3 == (kt-1)&3,
        // which every warp finished reading before the barrier above.
        if (kt + 3 < 32) {
            const int s = (kt + 3) & 3;
            const unsigned stB = (unsigned)(s * 2 * G_STB) << 1;
            const int k0 = (kt + 3) << 5;
            cpa16(sb + stB + aOff0,                Ab + (size_t)r0 * DIM + k0 + c0);
            cpa16(sb + stB + aOff1,                Ab + (size_t)r1 * DIM + k0 + c1);
            cpa16(sb + stB + (G_STB << 1) + aOff0, Wb + (size_t)r0 * DIM + k0 + c0);
            cpa16(sb + stB + (G_STB << 1) + aOff1, Wb + (size_t)r1 * DIM + k0 + c1);
            asm volatile("cp.async.commit_group;\n");
        }

        const unsigned aB = sb + ((unsigned)((kt & 3) * 2 * G_STB) << 1);
        const unsigned wB = aB + (G_STB << 1);
        #pragma unroll
        for (int s = 0; s < 2; s++) {
            const int kh = s << 4;
            unsigned af[4][4], bf[4][2];
            #pragma unroll
            for (int mt = 0; mt < 4; mt++)
                ldmx4(af[mt], aB +
                      (unsigned)(((aRow + (mt << 4))*LDH + kh + aKof) << 1));
            #pragma unroll
            for (int p = 0; p < 2; p++) {
                unsigned bx[4];
                ldmx4(bx, wB +
                      (unsigned)(((bRow + (p << 4))*LDH + kh + bKof) << 1));
                bf[2*p][0]   = bx[0]; bf[2*p][1]   = bx[1];
                bf[2*p+1][0] = bx[2]; bf[2*p+1][1] = bx[3];
            }
            #pragma unroll
            for (int mt = 0; mt < 4; mt++)
                #pragma unroll
                for (int nt = 0; nt < 4; nt++)
                    mma16(acc[mt][nt], af[mt][0], af[mt][1], af[mt][2], af[mt][3],
                          bf[nt][0], bf[nt][1]);
        }
    }

    #pragma unroll
    for (int mt = 0; mt < 4; mt++) {
        int r = m0 + wm + (mt << 4) + g;
        #pragma unroll
        for (int nt = 0; nt < 4; nt++) {
            int c = n0 + wn + (nt << 3) + (t << 1);
            float2 bv = *(const float2*)(bias + c);
            float o00 = acc[mt][nt][0] + bv.x, o01 = acc[mt][nt][1] + bv.y;
            float o10 = acc[mt][nt][2] + bv.x, o11 = acc[mt][nt][3] + bv.y;
            if (OMODE == 0) {
                float* C = (float*)Cv;
                *(float2*)(C + (size_t)r       * DIM + c) = make_float2(o00, o01);
                *(float2*)(C + (size_t)(r + 8) * DIM + c) = make_float2(o10, o11);
            } else {
                const float sc = (OMODE == 2) ? 0.125f : 1.0f;
                __half* C = (__half*)Cv;
                *(__half2*)(C + (size_t)r       * DIM + c) = __floats2half2_rn(o00*sc, o01*sc);
                *(__half2*)(C + (size_t)(r + 8) * DIM + c) = __floats2half2_rn(o10*sc, o11*sc);
            }
        }
    }
}

// ---------------------------------------------------------------------------
// attn_o (unchanged)
// ---------------------------------------------------------------------------
#define LDK 72

__global__ void __launch_bounds__(256,1) attn_o_fp16()
{
    __shared__ __half Ks[2][64*LDK];
    __shared__ __half Vs[2][64*LDK];

    const int tid  = threadIdx.x;
    const int lane = tid & 31, warp = tid >> 5;
    const int g = lane >> 2, t = lane & 3;
    const int t0 = blockIdx.x << 8;
    const int bh = blockIdx.y;
    const int b = bh >> 4, h = bh & 15;
    const size_t base = (size_t)b * SEQ * DIM + (size_t)h * HD;
    const __half* qb = g_qh + base;
    const __half* kb = g_kh + base;
    const __half* vb = g_vh + base;
    const int wr0 = t0 + (warp << 5);
    const int tile_t0 = (t0 >> 4) + (warp << 1);
    unsigned* ebw0 = g_expa + ((size_t)bh*(SEQ/16) + tile_t0    )*(SEQ/64)*512 + lane;
    unsigned* ebw1 = g_expa + ((size_t)bh*(SEQ/16) + tile_t0 + 1)*(SEQ/64)*512 + lane;

    unsigned qf[2][4][4];
    #pragma unroll
    for (int mf = 0; mf < 2; mf++) {
        const int r = wr0 + (mf << 4) + g;
        #pragma unroll
        for (int ks = 0; ks < 4; ks++) {
            const int c0 = (ks << 4) + (t << 1);
            qf[mf][ks][0] = *(const unsigned*)(qb + (size_t)r       * DIM + c0);
            qf[mf][ks][1] = *(const unsigned*)(qb + (size_t)(r + 8) * DIM + c0);
            qf[mf][ks][2] = *(const unsigned*)(qb + (size_t)r       * DIM + c0 + 8);
            qf[mf][ks][3] = *(const unsigned*)(qb + (size_t)(r + 8) * DIM + c0 + 8);
        }
    }

    float oacc[2][8][4];
    #pragma unroll
    for (int mf = 0; mf < 2; mf++)
        #pragma unroll
        for (int i = 0; i < 8; i++)
            #pragma unroll
            for (int v = 0; v < 4; v++) oacc[mf][i][v] = 0.f;
    float lp[2][2] = {{0.f,0.f},{0.f,0.f}};

    const unsigned ksb[2] = { smem_u32(Ks[0]), smem_u32(Ks[1]) };
    const unsigned vsb[2] = { smem_u32(Vs[0]), smem_u32(Vs[1]) };
    const int mi = lane >> 3, mj = lane & 7;

    const int r0c = tid >> 3,         c0c = (tid & 7) << 3;
    const int r1c = (tid + 256) >> 3, c1c = c0c;

    cpa16(ksb[0] + ((r0c*LDK + c0c) << 1), kb + (size_t)r0c * DIM + c0c);
    cpa16(ksb[0] + ((r1c*LDK + c1c) << 1), kb + (size_t)r1c * DIM + c1c);
    cpa16(vsb[0] + ((r0c*LDK + c0c) << 1), vb + (size_t)r0c * DIM + c0c);
    cpa16(vsb[0] + ((r1c*LDK + c1c) << 1), vb + (size_t)r1c * DIM + c1c);
    asm volatile("cp.async.commit_group;\n");

    for (int i = 0; i < SEQ/64; i++) {
        const int st = i & 1;
        if (i + 1 < SEQ/64) {
            const int ns = (i + 1) & 1;
            const size_t nb = (size_t)((i + 1) << 6) * DIM;
            cpa16(ksb[ns] + ((r0c*LDK + c0c) << 1), kb + nb + (size_t)r0c * DIM + c0c);
            cpa16(ksb[ns] + ((r1c*LDK + c1c) << 1), kb + nb + (size_t)r1c * DIM + c1c);
            cpa16(vsb[ns] + ((r0c*LDK + c0c) << 1), vb + nb + (size_t)r0c * DIM + c0c);
            cpa16(vsb[ns] + ((r1c*LDK + c1c) << 1), vb + nb + (size_t)r1c * DIM + c1c);
            asm volatile("cp.async.commit_group;\n");
            asm volatile("cp.async.wait_group 1;\n");
        } else {
            asm volatile("cp.async.wait_group 0;\n");
        }
        __syncthreads();

        const __half* ksp = Ks[st];
        unsigned* eb0 = ebw0 + (size_t)i * 512;
        unsigned* eb1 = ebw1 + (size_t)i * 512;

        #pragma unroll
        for (int ch = 0; ch < 2; ch++) {
            float sc[2][4][4];
            #pragma unroll
            for (int mf = 0; mf < 2; mf++)
                #pragma unroll
                for (int j = 0; j < 4; j++)
                    #pragma unroll
                    for (int v = 0; v < 4; v++) sc[mf][j][v] = 0.f;
            #pragma unroll
            for (int ks = 0; ks < 4; ks++) {
                const int kc = (ks << 4) + (t << 1);
                unsigned b0[4], b1[4];
                #pragma unroll
                for (int nt = 0; nt < 4; nt++) {
                    const int r = (ch << 5) + (nt << 3) + g;
                    b0[nt] = *(const unsigned*)&ksp[r*LDK + kc];
                    b1[nt] = *(const unsigned*)&ksp[r*LDK + kc + 8];
                }
                #pragma unroll
                for (int mf = 0; mf < 2; mf++)
                    #pragma unroll
                    for (int nt = 0; nt < 4; nt++)
                        mma16(sc[mf][nt], qf[mf][ks][0], qf[mf][ks][1],
                              qf[mf][ks][2], qf[mf][ks][3], b0[nt], b1[nt]);
            }

            unsigned ph[2][4][2];
            #pragma unroll
            for (int mf = 0; mf < 2; mf++) {
                unsigned* ebm = mf ? eb1 : eb0;
                #pragma unroll
                for (int nt = 0; nt < 4; nt++) {
                    float e0 = __expf(fminf(sc[mf][nt][0], 11.f));
                    float e1 = __expf(fminf(sc[mf][nt][1], 11.f));
                    float e2 = __expf(fminf(sc[mf][nt][2], 11.f));
                    float e3 = __expf(fminf(sc[mf][nt][3], 11.f));
                    lp[mf][0] += e0 + e1;
                    lp[mf][1] += e2 + e3;
                    ph[mf][nt][0] = h2u(__floats2half2_rn(e0, e1));
                    ph[mf][nt][1] = h2u(__floats2half2_rn(e2, e3));
                    const int w = (((ch << 2) + nt) << 1);
                    ebm[(w    ) << 5] = ph[mf][nt][0];
                    ebm[(w + 1) << 5] = ph[mf][nt][1];
                }
            }

            #pragma unroll
            for (int ks2 = 0; ks2 < 2; ks2++) {
                #pragma unroll
                for (int p = 0; p < 4; p++) {
                    const int vrow = (ch << 5) + (ks2 << 4) + ((mi & 1) << 3) + mj;
                    const int vcol = (p << 4) + ((mi >> 1) << 3);
                    unsigned r[4];
                    ldmx4t(r, vsb[st] + (unsigned)((vrow*LDK + vcol) << 1));
                    #pragma unroll
                    for (int mf = 0; mf < 2; mf++) {
                        mma16(oacc[mf][2*p],   ph[mf][2*ks2][0], ph[mf][2*ks2][1],
                              ph[mf][2*ks2+1][0], ph[mf][2*ks2+1][1], r[0], r[1]);
                        mma16(oacc[mf][2*p+1], ph[mf][2*ks2][0], ph[mf][2*ks2][1],
                              ph[mf][2*ks2+1][0], ph[mf][2*ks2+1][1], r[2], r[3]);
                    }
                }
            }
        }
        __syncthreads();
    }

    #pragma unroll
    for (int mf = 0; mf < 2; mf++) {
        float l0 = lp[mf][0], l1 = lp[mf][1];
        l0 += __shfl_xor_sync(0xffffffffu, l0, 1);
        l0 += __shfl_xor_sync(0xffffffffu, l0, 2);
        l1 += __shfl_xor_sync(0xffffffffu, l1, 1);
        l1 += __shfl_xor_sync(0xffffffffu, l1, 2);
        const float rl0 = 1.0f / l0;
        const float rl1 = 1.0f / l1;
        const int row0 = wr0 + (mf << 4) + g;
        if (t == 0) {
            g_rl[(size_t)bh * SEQ + row0]     = rl0;
            g_rl[(size_t)bh * SEQ + row0 + 8] = rl1;
        }
        #pragma unroll
        for (int nt = 0; nt < 8; nt++) {
            const int c = h*HD + (nt << 3) + (t << 1);
            *(__half2*)(g_ohh + (size_t)(b*SEQ + row0)     * DIM + c) =
                __floats2half2_rn(oacc[mf][nt][0]*rl0, oacc[mf][nt][1]*rl0);
            *(__half2*)(g_ohh + (size_t)(b*SEQ + row0 + 8) * DIM + c) =
                __floats2half2_rn(oacc[mf][nt][2]*rl1, oacc[mf][nt][3]*rl1);
        }
    }
}

// ---------------------------------------------------------------------------
// head_reduce (unchanged from round 9)
// ---------------------------------------------------------------------------
__global__ void __launch_bounds__(256) head_reduce(float* __restrict__ wout)
{
    __shared__ float tr[8][16][66];
    const int lane = threadIdx.x & 31, warp = threadIdx.x >> 5;
    const int blk = blockIdx.x;
    const int b = blk >> 7, tile_t = blk & 127;
    const int r = (lane & 7) + (((lane >> 3) & 1) << 3);
    const int cbase = (lane >> 4) << 3;
    const float invH = 1.0f / (float)HEADS;

    for (int ts = warp; ts < SEQ/64; ts += 8) {
        float2 acc[4][4];
        #pragma unroll
        for (int k = 0; k < 4; k++)
            #pragma unroll
            for (int j = 0; j < 4; j++) acc[k][j] = make_float2(0.f, 0.f);

        for (int h = 0; h < HEADS; h++) {
            const int bh = b * HEADS + h;
            const size_t tb4 = ((((size_t)bh*(SEQ/16) + tile_t)*(SEQ/64) + ts)*512) >> 2;
            const uint4* p = (const uint4*)g_expa + tb4 + lane;
            const float rl = __ldg(&g_rl[(size_t)bh*SEQ + (tile_t << 4) + r]);
            #pragma unroll
            for (int k = 0; k < 4; k++) {
                uint4 u = __ldg(p + (k << 5));
                float2 f0 = __half22float2(*(__half2*)&u.x);
                float2 f1 = __half22float2(*(__half2*)&u.y);
                float2 f2 = __half22float2(*(__half2*)&u.z);
                float2 f3 = __half22float2(*(__half2*)&u.w);
                acc[k][0].x += f0.x*rl; acc[k][0].y += f0.y*rl;
                acc[k][1].x += f1.x*rl; acc[k][1].y += f1.y*rl;
                acc[k][2].x += f2.x*rl; acc[k][2].y += f2.y*rl;
                acc[k][3].x += f3.x*rl; acc[k][3].y += f3.y*rl;
            }
        }

        #pragma unroll
        for (int k = 0; k < 4; k++)
            #pragma unroll
            for (int j = 0; j < 4; j++) {
                const int c = cbase + (k << 4) + (j << 1);
                tr[warp][r][c]     = acc[k][j].x * invH;
                tr[warp][r][c + 1] = acc[k][j].y * invH;
            }
        __syncwarp();
        #pragma unroll
        for (int rr = 0; rr < 16; rr++) {
            float2 v = *(float2*)&tr[warp][rr][lane << 1];
            *(float2*)(wout + ((size_t)b*SEQ + (tile_t<<4) + rr)*SEQ + (ts<<6) + (lane<<1)) = v;
        }
        __syncwarp();
    }
}

// ---------------------------------------------------------------------------
extern "C" void kernel_launch(void* const* d_in, const int* in_sizes, int n_in,
                              void* d_out, int out_size)
{
    const float* Q  = (const float*)d_in[0];
    const float* K  = (const float*)d_in[1];
    const float* V  = (const float*)d_in[2];
    const float* Wq = (const float*)d_in[3];
    const float* bq = (const float*)d_in[4];
    const float* Wk = (const float*)d_in[5];
    const float* bk = (const float*)d_in[6];
    const float* Wv = (const float*)d_in[7];
    const float* bv = (const float*)d_in[8];
    const float* Wo = (const float*)d_in[9];
    const float* bo = (const float*)d_in[10];

    float* outO = (float*)d_out;                       // [B,T,D]
    float* outW = outO + (size_t)BATCH * SEQ * DIM;    // [B,T,T]

    __half *pin, *pw, *pq, *pk, *pv, *poh;
    cudaGetSymbolAddress((void**)&pin, g_in);
    cudaGetSymbolAddress((void**)&pw,  g_w);
    cudaGetSymbolAddress((void**)&pq,  g_qh);
    cudaGetSymbolAddress((void**)&pk,  g_kh);
    cudaGetSymbolAddress((void**)&pv,  g_vh);
    cudaGetSymbolAddress((void**)&poh, g_ohh);

    cudaFuncSetAttribute(gemm_hh<0>, cudaFuncAttributeMaxDynamicSharedMemorySize, G_SMEM_BYTES);
    cudaFuncSetAttribute(gemm_hh<1>, cudaFuncAttributeMaxDynamicSharedMemorySize, G_SMEM_BYTES);
    cudaFuncSetAttribute(gemm_hh<2>, cudaFuncAttributeMaxDynamicSharedMemorySize, G_SMEM_BYTES);

    cvt_all<<<dim3(256, 7), 256>>>(Q, K, V, Wq, Wk, Wv, Wo);

    dim3 pg(DIM/128, MTOT/128);        // (8, 64)
    gemm_hh<2><<<pg, 256, G_SMEM_BYTES>>>(pin,              pw,             bq, pq);
    gemm_hh<1><<<pg, 256, G_SMEM_BYTES>>>(pin +   MTOT*DIM, pw +   DIM*DIM, bk, pk);
    gemm_hh<1><<<pg, 256, G_SMEM_BYTES>>>(pin + 2*MTOT*DIM, pw + 2*DIM*DIM, bv, pv);

    attn_o_fp16<<<dim3(SEQ/256, BATCH*HEADS), 256>>>();

    // Wo-GEMM at launch index 5 so ncu (-s 5 -c 1) profiles the GEMM
    gemm_hh<0><<<pg, 256, G_SMEM_BYTES>>>(poh, pw + 3*DIM*DIM, bo, outO);

    head_reduce<<<BATCH*(SEQ/16), 256>>>(outW);
}

// round 13
// speedup vs baseline: 1.2453x; 1.0994x over previous
#include <cuda_runtime.h>
#include <cuda_fp16.h>
#include <cstdint>
#include <math.h>

#define BATCH 4
#define SEQ   2048
#define DIM   1024
#define HEADS 16
#define HD    64
#define MTOT  (BATCH*SEQ)   // 8192

// Scratch (allocation-free rule: __device__ globals)
__device__ __half g_in [3][MTOT*DIM];     // fp16 copies of Q,K,V inputs
__device__ __half g_w  [4][DIM*DIM];      // fp16 copies of Wq,Wk,Wv,Wo
__device__ __half g_qh [MTOT*DIM];        // projected q (pre-scaled 0.125)
__device__ __half g_kh [MTOT*DIM];
__device__ __half g_vh [MTOT*DIM];
__device__ __half g_ohh[MTOT*DIM];        // attention output heads
__device__ float  g_rl [BATCH*HEADS*SEQ];
// exp(scores), FRAGMENT-BLOCKED: tile (bh,tile_t,tile_s) of 16x64 halves
// = 512 words; word addr = tile*512 + word_idx*32 + lane.
__device__ unsigned g_expa[(size_t)BATCH*HEADS*(SEQ/16)*(SEQ/64)*512];

// ---------------------------------------------------------------------------
// helpers
// ---------------------------------------------------------------------------
__device__ __forceinline__ void mma16(float c[4],
    unsigned a0, unsigned a1, unsigned a2, unsigned a3,
    unsigned b0, unsigned b1)
{
    asm volatile(
      "mma.sync.aligned.m16n8k16.row.col.f32.f16.f16.f32 "
      "{%0,%1,%2,%3},{%4,%5,%6,%7},{%8,%9},{%0,%1,%2,%3};"
      : "+f"(c[0]), "+f"(c[1]), "+f"(c[2]), "+f"(c[3])
      : "r"(a0), "r"(a1), "r"(a2), "r"(a3), "r"(b0), "r"(b1));
}
__device__ __forceinline__ void ldmx4(unsigned r[4], unsigned addr)
{
    asm volatile(
      "ldmatrix.sync.aligned.m8n8.x4.shared.b16 {%0,%1,%2,%3}, [%4];"
      : "=r"(r[0]), "=r"(r[1]), "=r"(r[2]), "=r"(r[3]) : "r"(addr));
}
__device__ __forceinline__ void ldmx4t(unsigned r[4], unsigned addr)
{
    asm volatile(
      "ldmatrix.sync.aligned.m8n8.x4.trans.shared.b16 {%0,%1,%2,%3}, [%4];"
      : "=r"(r[0]), "=r"(r[1]), "=r"(r[2]), "=r"(r[3]) : "r"(addr));
}
__device__ __forceinline__ unsigned h2u(__half2 h) { return *(unsigned*)&h; }
__device__ __forceinline__ void cpa16(unsigned dst, const void* src) {
    asm volatile("cp.async.cg.shared.global [%0], [%1], 16;\n" :: "r"(dst), "l"(src));
}
__device__ __forceinline__ uint32_t smem_u32(const void* p) {
    uint32_t a;
    asm("{ .reg .u64 t; cvta.to.shared.u64 t, %1; cvt.u32.u64 %0, t; }"
        : "=r"(a) : "l"(p));
    return a;
}

// ---------------------------------------------------------------------------
// single fp32->fp16 convert covering all 7 tensors (grid.y selects)
// ---------------------------------------------------------------------------
__global__ void __launch_bounds__(256) cvt_all(
    const float* q, const float* k, const float* v,
    const float* wq, const float* wk, const float* wv, const float* wo)
{
    const int y = blockIdx.y;
    const float* src;
    __half* dst;
    int n4;
    switch (y) {
        case 0: src = q;  dst = g_in[0]; n4 = MTOT*DIM/4; break;
        case 1: src = k;  dst = g_in[1]; n4 = MTOT*DIM/4; break;
        case 2: src = v;  dst = g_in[2]; n4 = MTOT*DIM/4; break;
        case 3: src = wq; dst = g_w[0];  n4 = DIM*DIM/4;  break;
        case 4: src = wk; dst = g_w[1];  n4 = DIM*DIM/4;  break;
        case 5: src = wv; dst = g_w[2];  n4 = DIM*DIM/4;  break;
        default: src = wo; dst = g_w[3]; n4 = DIM*DIM/4;  break;
    }
    for (int i = blockIdx.x*256 + threadIdx.x; i < n4; i += gridDim.x*256) {
        float4 f = *(const float4*)(src + (size_t)i*4);
        *(__half2*)(dst + (size_t)i*4)     = __floats2half2_rn(f.x, f.y);
        *(__half2*)(dst + (size_t)i*4 + 2) = __floats2half2_rn(f.z, f.w);
    }
}

// ---------------------------------------------------------------------------
// fp16 NT GEMM body, 4-stage cp.async pipeline, one barrier per k-tile.
// Block tile 128x128, BK=32, 256 threads, warp tile 64x32.
// omode: 0 fp32-out, 1 fp16-out, 2 fp16-out scaled 0.125.
// ---------------------------------------------------------------------------
#define LDH   40
#define G_STB (128*LDH)                 // halves per stage-operand (10240 B)
#define G_SMEM_BYTES (4 * 2 * G_STB * 2)  // 81920

__device__ __forceinline__ void gemm_body(
    const __half* __restrict__ A, const __half* __restrict__ W,
    const float* __restrict__ bias, void* __restrict__ Cv,
    unsigned sb, int m0, int n0, int omode)
{
    const int tid  = threadIdx.x;
    const int lane = tid & 31, warp = tid >> 5;
    const int g = lane >> 2, t = lane & 3;
    const int wm = (warp >> 2) << 6, wn = (warp & 3) << 5;
    const __half* Ab = A + (size_t)m0 * DIM;
    const __half* Wb = W + (size_t)n0 * DIM;

    // cp.async coords: 512 16B-chunks per operand per stage, 2 per thread
    const int ch0 = tid << 1, ch1 = ch0 + 1;
    const int r0 = ch0 >> 2, c0 = (ch0 & 3) << 3;
    const int r1 = ch1 >> 2, c1 = (ch1 & 3) << 3;
    const unsigned aOff0 = (unsigned)((r0*LDH + c0) << 1);
    const unsigned aOff1 = (unsigned)((r1*LDH + c1) << 1);

    // ldmatrix lane-address components
    const int aRow = wm + (lane & 15);                 // + mt*16
    const int aKof = (lane >> 4) << 3;                 // + s*16
    const int bRow = wn + ((lane >> 4) << 3) + (lane & 7);   // + p*16
    const int bKof = ((lane >> 3) & 1) << 3;           // + s*16

    float acc[4][4][4];
    #pragma unroll
    for (int i = 0; i < 4; i++)
        #pragma unroll
        for (int j = 0; j < 4; j++)
            #pragma unroll
            for (int v = 0; v < 4; v++) acc[i][j][v] = 0.f;

    // prologue: k-tiles 0..2 -> stages 0..2
    #pragma unroll
    for (int s = 0; s < 3; s++) {
        const unsigned stB = (unsigned)(s * 2 * G_STB) << 1;   // bytes
        const int k0 = s << 5;
        cpa16(sb + stB + aOff0,                    Ab + (size_t)r0 * DIM + k0 + c0);
        cpa16(sb + stB + aOff1,                    Ab + (size_t)r1 * DIM + k0 + c1);
        cpa16(sb + stB + (G_STB << 1) + aOff0,     Wb + (size_t)r0 * DIM + k0 + c0);
        cpa16(sb + stB + (G_STB << 1) + aOff1,     Wb + (size_t)r1 * DIM + k0 + c1);
        asm volatile("cp.async.commit_group;\n");
    }

    for (int kt = 0; kt < 32; kt++) {
        if (kt <= 29)      asm volatile("cp.async.wait_group 2;\n");
        else if (kt == 30) asm volatile("cp.async.wait_group 1;\n");
        else               asm volatile("cp.async.wait_group 0;\n");
        __syncthreads();

        // loads for kt+3 target buffer (kt+3)&3 == (kt-1)&3, finished pre-barrier
        if (kt + 3 < 32) {
            const int s = (kt + 3) & 3;
            const unsigned stB = (unsigned)(s * 2 * G_STB) << 1;
            const int k0 = (kt + 3) << 5;
            cpa16(sb + stB + aOff0,                Ab + (size_t)r0 * DIM + k0 + c0);
            cpa16(sb + stB + aOff1,                Ab + (size_t)r1 * DIM + k0 + c1);
            cpa16(sb + stB + (G_STB << 1) + aOff0, Wb + (size_t)r0 * DIM + k0 + c0);
            cpa16(sb + stB + (G_STB << 1) + aOff1, Wb + (size_t)r1 * DIM + k0 + c1);
            asm volatile("cp.async.commit_group;\n");
        }

        const unsigned aB = sb + ((unsigned)((kt & 3) * 2 * G_STB) << 1);
        const unsigned wB = aB + (G_STB << 1);
        #pragma unroll
        for (int s = 0; s < 2; s++) {
            const int kh = s << 4;
            unsigned af[4][4], bf[4][2];
            #pragma unroll
            for (int mt = 0; mt < 4; mt++)
                ldmx4(af[mt], aB +
                      (unsigned)(((aRow + (mt << 4))*LDH + kh + aKof) << 1));
            #pragma unroll
            for (int p = 0; p < 2; p++) {
                unsigned bx[4];
                ldmx4(bx, wB +
                      (unsigned)(((bRow + (p << 4))*LDH + kh + bKof) << 1));
                bf[2*p][0]   = bx[0]; bf[2*p][1]   = bx[1];
                bf[2*p+1][0] = bx[2]; bf[2*p+1][1] = bx[3];
            }
            #pragma unroll
            for (int mt = 0; mt < 4; mt++)
                #pragma unroll
                for (int nt = 0; nt < 4; nt++)
                    mma16(acc[mt][nt], af[mt][0], af[mt][1], af[mt][2], af[mt][3],
                          bf[nt][0], bf[nt][1]);
        }
    }

    #pragma unroll
    for (int mt = 0; mt < 4; mt++) {
        int r = m0 + wm + (mt << 4) + g;
        #pragma unroll
        for (int nt = 0; nt < 4; nt++) {
            int c = n0 + wn + (nt << 3) + (t << 1);
            float2 bv = *(const float2*)(bias + c);
            float o00 = acc[mt][nt][0] + bv.x, o01 = acc[mt][nt][1] + bv.y;
            float o10 = acc[mt][nt][2] + bv.x, o11 = acc[mt][nt][3] + bv.y;
            if (omode == 0) {
                float* C = (float*)Cv;
                *(float2*)(C + (size_t)r       * DIM + c) = make_float2(o00, o01);
                *(float2*)(C + (size_t)(r + 8) * DIM + c) = make_float2(o10, o11);
            } else {
                const float scl = (omode == 2) ? 0.125f : 1.0f;
                __half* C = (__half*)Cv;
                *(__half2*)(C + (size_t)r       * DIM + c) = __floats2half2_rn(o00*scl, o01*scl);
                *(__half2*)(C + (size_t)(r + 8) * DIM + c) = __floats2half2_rn(o10*scl, o11*scl);
            }
        }
    }
}

// ---------------------------------------------------------------------------
// merged q/k/v projection: grid (8, 64, 3); z selects tensor set
// ---------------------------------------------------------------------------
__global__ void __launch_bounds__(256,2) gemm_proj(
    const float* __restrict__ bq, const float* __restrict__ bk,
    const float* __restrict__ bv)
{
    extern __shared__ __half smh[];
    const unsigned sb = smem_u32(smh);
    const int z = blockIdx.z;
    const float* bias = (z == 0) ? bq : (z == 1) ? bk : bv;
    __half* C = (z == 0) ? g_qh : (z == 1) ? g_kh : g_vh;
    gemm_body(g_in[z], g_w[z], bias, C, sb,
              blockIdx.y << 7, blockIdx.x << 7, (z == 0) ? 2 : 1);
}

// ---------------------------------------------------------------------------
// fused Wo-GEMM + head_reduce fat kernel: blocks 0..511 GEMM, 512..1023 reduce
// (reduce aliases its transpose buffer into the same dynamic smem)
// ---------------------------------------------------------------------------
__global__ void __launch_bounds__(256,2) wo_and_weight(
    const float* __restrict__ bo, float* __restrict__ outO,
    float* __restrict__ outW)
{
    extern __shared__ __half smh[];
    if (blockIdx.x < 512) {
        const unsigned sb = smem_u32(smh);
        gemm_body(g_ohh, g_w[3], bo, outO, sb,
                  (blockIdx.x >> 3) << 7, (blockIdx.x & 7) << 7, 0);
        return;
    }

    // ---- head_reduce body (tr in dynamic smem: [8][16][66] floats) ----
    float* trb = (float*)smh;
    const int lane = threadIdx.x & 31, warp = threadIdx.x >> 5;
    const int blk = blockIdx.x - 512;
    const int b = blk >> 7, tile_t = blk & 127;
    const int r = (lane & 7) + (((lane >> 3) & 1) << 3);
    const int cbase = (lane >> 4) << 3;
    const float invH = 1.0f / (float)HEADS;
    float* tr = trb + warp * 16 * 66;

    for (int ts = warp; ts < SEQ/64; ts += 8) {
        float2 acc[4][4];
        #pragma unroll
        for (int k = 0; k < 4; k++)
            #pragma unroll
            for (int j = 0; j < 4; j++) acc[k][j] = make_float2(0.f, 0.f);

        for (int h = 0; h < HEADS; h++) {
            const int bh = b * HEADS + h;
            const size_t tb4 = ((((size_t)bh*(SEQ/16) + tile_t)*(SEQ/64) + ts)*512) >> 2;
            const uint4* p = (const uint4*)g_expa + tb4 + lane;
            const float rl = __ldg(&g_rl[(size_t)bh*SEQ + (tile_t << 4) + r]);
            #pragma unroll
            for (int k = 0; k < 4; k++) {
                uint4 u = __ldg(p + (k << 5));
                float2 f0 = __half22float2(*(__half2*)&u.x);
                float2 f1 = __half22float2(*(__half2*)&u.y);
                float2 f2 = __half22float2(*(__half2*)&u.z);
                float2 f3 = __half22float2(*(__half2*)&u.w);
                acc[k][0].x += f0.x*rl; acc[k][0].y += f0.y*rl;
                acc[k][1].x += f1.x*rl; acc[k][1].y += f1.y*rl;
                acc[k][2].x += f2.x*rl; acc[k][2].y += f2.y*rl;
                acc[k][3].x += f3.x*rl; acc[k][3].y += f3.y*rl;
            }
        }

        // transpose via smem (row fixed per lane; cols = cbase+16k+2j)
        #pragma unroll
        for (int k = 0; k < 4; k++)
            #pragma unroll
            for (int j = 0; j < 4; j++) {
                const int c = cbase + (k << 4) + (j << 1);
                tr[r*66 + c]     = acc[k][j].x * invH;
                tr[r*66 + c + 1] = acc[k][j].y * invH;
            }
        __syncwarp();
        #pragma unroll
        for (int rr = 0; rr < 16; rr++) {
            float2 v = *(float2*)&tr[rr*66 + (lane << 1)];
            *(float2*)(outW + ((size_t)b*SEQ + (tile_t<<4) + rr)*SEQ + (ts<<6) + (lane<<1)) = v;
        }
        __syncwarp();
    }
}

// ---------------------------------------------------------------------------
// attn_o (unchanged from rounds 6-12)
// ---------------------------------------------------------------------------
#define LDK 72

__global__ void __launch_bounds__(256,1) attn_o_fp16()
{
    __shared__ __half Ks[2][64*LDK];
    __shared__ __half Vs[2][64*LDK];

    const int tid  = threadIdx.x;
    const int lane = tid & 31, warp = tid >> 5;
    const int g = lane >> 2, t = lane & 3;
    const int t0 = blockIdx.x << 8;
    const int bh = blockIdx.y;
    const int b = bh >> 4, h = bh & 15;
    const size_t base = (size_t)b * SEQ * DIM + (size_t)h * HD;
    const __half* qb = g_qh + base;
    const __half* kb = g_kh + base;
    const __half* vb = g_vh + base;
    const int wr0 = t0 + (warp << 5);
    const int tile_t0 = (t0 >> 4) + (warp << 1);
    unsigned* ebw0 = g_expa + ((size_t)bh*(SEQ/16) + tile_t0    )*(SEQ/64)*512 + lane;
    unsigned* ebw1 = g_expa + ((size_t)bh*(SEQ/16) + tile_t0 + 1)*(SEQ/64)*512 + lane;

    unsigned qf[2][4][4];
    #pragma unroll
    for (int mf = 0; mf < 2; mf++) {
        const int r = wr0 + (mf << 4) + g;
        #pragma unroll
        for (int ks = 0; ks < 4; ks++) {
            const int c0 = (ks << 4) + (t << 1);
            qf[mf][ks][0] = *(const unsigned*)(qb + (size_t)r       * DIM + c0);
            qf[mf][ks][1] = *(const unsigned*)(qb + (size_t)(r + 8) * DIM + c0);
            qf[mf][ks][2] = *(const unsigned*)(qb + (size_t)r       * DIM + c0 + 8);
            qf[mf][ks][3] = *(const unsigned*)(qb + (size_t)(r + 8) * DIM + c0 + 8);
        }
    }

    float oacc[2][8][4];
    #pragma unroll
    for (int mf = 0; mf < 2; mf++)
        #pragma unroll
        for (int i = 0; i < 8; i++)
            #pragma unroll
            for (int v = 0; v < 4; v++) oacc[mf][i][v] = 0.f;
    float lp[2][2] = {{0.f,0.f},{0.f,0.f}};

    const unsigned ksb[2] = { smem_u32(Ks[0]), smem_u32(Ks[1]) };
    const unsigned vsb[2] = { smem_u32(Vs[0]), smem_u32(Vs[1]) };
    const int mi = lane >> 3, mj = lane & 7;

    const int r0c = tid >> 3,         c0c = (tid & 7) << 3;
    const int r1c = (tid + 256) >> 3, c1c = c0c;

    cpa16(ksb[0] + ((r0c*LDK + c0c) << 1), kb + (size_t)r0c * DIM + c0c);
    cpa16(ksb[0] + ((r1c*LDK + c1c) << 1), kb + (size_t)r1c * DIM + c1c);
    cpa16(vsb[0] + ((r0c*LDK + c0c) << 1), vb + (size_t)r0c * DIM + c0c);
    cpa16(vsb[0] + ((r1c*LDK + c1c) << 1), vb + (size_t)r1c * DIM + c1c);
    asm volatile("cp.async.commit_group;\n");

    for (int i = 0; i < SEQ/64; i++) {
        const int st = i & 1;
        if (i + 1 < SEQ/64) {
            const int ns = (i + 1) & 1;
            const size_t nb = (size_t)((i + 1) << 6) * DIM;
            cpa16(ksb[ns] + ((r0c*LDK + c0c) << 1), kb + nb + (size_t)r0c * DIM + c0c);
            cpa16(ksb[ns] + ((r1c*LDK + c1c) << 1), kb + nb + (size_t)r1c * DIM + c1c);
            cpa16(vsb[ns] + ((r0c*LDK + c0c) << 1), vb + nb + (size_t)r0c * DIM + c0c);
            cpa16(vsb[ns] + ((r1c*LDK + c1c) << 1), vb + nb + (size_t)r1c * DIM + c1c);
            asm volatile("cp.async.commit_group;\n");
            asm volatile("cp.async.wait_group 1;\n");
        } else {
            asm volatile("cp.async.wait_group 0;\n");
        }
        __syncthreads();

        const __half* ksp = Ks[st];
        unsigned* eb0 = ebw0 + (size_t)i * 512;
        unsigned* eb1 = ebw1 + (size_t)i * 512;

        #pragma unroll
        for (int ch = 0; ch < 2; ch++) {
            float sc[2][4][4];
            #pragma unroll
            for (int mf = 0; mf < 2; mf++)
                #pragma unroll
                for (int j = 0; j < 4; j++)
                    #pragma unroll
                    for (int v = 0; v < 4; v++) sc[mf][j][v] = 0.f;
            #pragma unroll
            for (int ks = 0; ks < 4; ks++) {
                const int kc = (ks << 4) + (t << 1);
                unsigned b0[4], b1[4];
                #pragma unroll
                for (int nt = 0; nt < 4; nt++) {
                    const int r = (ch << 5) + (nt << 3) + g;
                    b0[nt] = *(const unsigned*)&ksp[r*LDK + kc];
                    b1[nt] = *(const unsigned*)&ksp[r*LDK + kc + 8];
                }
                #pragma unroll
                for (int mf = 0; mf < 2; mf++)
                    #pragma unroll
                    for (int nt = 0; nt < 4; nt++)
                        mma16(sc[mf][nt], qf[mf][ks][0], qf[mf][ks][1],
                              qf[mf][ks][2], qf[mf][ks][3], b0[nt], b1[nt]);
            }

            unsigned ph[2][4][2];
            #pragma unroll
            for (int mf = 0; mf < 2; mf++) {
                unsigned* ebm = mf ? eb1 : eb0;
                #pragma unroll
                for (int nt = 0; nt < 4; nt++) {
                    float e0 = __expf(fminf(sc[mf][nt][0], 11.f));
                    float e1 = __expf(fminf(sc[mf][nt][1], 11.f));
                    float e2 = __expf(fminf(sc[mf][nt][2], 11.f));
                    float e3 = __expf(fminf(sc[mf][nt][3], 11.f));
                    lp[mf][0] += e0 + e1;
                    lp[mf][1] += e2 + e3;
                    ph[mf][nt][0] = h2u(__floats2half2_rn(e0, e1));
                    ph[mf][nt][1] = h2u(__floats2half2_rn(e2, e3));
                    const int w = (((ch << 2) + nt) << 1);
                    ebm[(w    ) << 5] = ph[mf][nt][0];
                    ebm[(w + 1) << 5] = ph[mf][nt][1];
                }
            }

            #pragma unroll
            for (int ks2 = 0; ks2 < 2; ks2++) {
                #pragma unroll
                for (int p = 0; p < 4; p++) {
                    const int vrow = (ch << 5) + (ks2 << 4) + ((mi & 1) << 3) + mj;
                    const int vcol = (p << 4) + ((mi >> 1) << 3);
                    unsigned r[4];
                    ldmx4t(r, vsb[st] + (unsigned)((vrow*LDK + vcol) << 1));
                    #pragma unroll
                    for (int mf = 0; mf < 2; mf++) {
                        mma16(oacc[mf][2*p],   ph[mf][2*ks2][0], ph[mf][2*ks2][1],
                              ph[mf][2*ks2+1][0], ph[mf][2*ks2+1][1], r[0], r[1]);
                        mma16(oacc[mf][2*p+1], ph[mf][2*ks2][0], ph[mf][2*ks2][1],
                              ph[mf][2*ks2+1][0], ph[mf][2*ks2+1][1], r[2], r[3]);
                    }
                }
            }
        }
        __syncthreads();
    }

    #pragma unroll
    for (int mf = 0; mf < 2; mf++) {
        float l0 = lp[mf][0], l1 = lp[mf][1];
        l0 += __shfl_xor_sync(0xffffffffu, l0, 1);
        l0 += __shfl_xor_sync(0xffffffffu, l0, 2);
        l1 += __shfl_xor_sync(0xffffffffu, l1, 1);
        l1 += __shfl_xor_sync(0xffffffffu, l1, 2);
        const float rl0 = 1.0f / l0;
        const float rl1 = 1.0f / l1;
        const int row0 = wr0 + (mf << 4) + g;
        if (t == 0) {
            g_rl[(size_t)bh * SEQ + row0]     = rl0;
            g_rl[(size_t)bh * SEQ + row0 + 8] = rl1;
        }
        #pragma unroll
        for (int nt = 0; nt < 8; nt++) {
            const int c = h*HD + (nt << 3) + (t << 1);
            *(__half2*)(g_ohh + (size_t)(b*SEQ + row0)     * DIM + c) =
                __floats2half2_rn(oacc[mf][nt][0]*rl0, oacc[mf][nt][1]*rl0);
            *(__half2*)(g_ohh + (size_t)(b*SEQ + row0 + 8) * DIM + c) =
                __floats2half2_rn(oacc[mf][nt][2]*rl1, oacc[mf][nt][3]*rl1);
        }
    }
}

// ---------------------------------------------------------------------------
extern "C" void kernel_launch(void* const* d_in, const int* in_sizes, int n_in,
                              void* d_out, int out_size)
{
    const float* Q  = (const float*)d_in[0];
    const float* K  = (const float*)d_in[1];
    const float* V  = (const float*)d_in[2];
    const float* bq = (const float*)d_in[4];
    const float* bk = (const float*)d_in[6];
    const float* bv = (const float*)d_in[8];
    const float* Wq = (const float*)d_in[3];
    const float* Wk = (const float*)d_in[5];
    const float* Wv = (const float*)d_in[7];
    const float* Wo = (const float*)d_in[9];
    const float* bo = (const float*)d_in[10];

    float* outO = (float*)d_out;                       // [B,T,D]
    float* outW = outO + (size_t)BATCH * SEQ * DIM;    // [B,T,T]

    cudaFuncSetAttribute(gemm_proj,     cudaFuncAttributeMaxDynamicSharedMemorySize, G_SMEM_BYTES);
    cudaFuncSetAttribute(wo_and_weight, cudaFuncAttributeMaxDynamicSharedMemorySize, G_SMEM_BYTES);

    cvt_all<<<dim3(256, 7), 256>>>(Q, K, V, Wq, Wk, Wv, Wo);

    // merged q/k/v projections: grid (8, 64, 3)
    gemm_proj<<<dim3(DIM/128, MTOT/128, 3), 256, G_SMEM_BYTES>>>(bq, bk, bv);

    attn_o_fp16<<<dim3(SEQ/256, BATCH*HEADS), 256>>>();

    // fused Wo-GEMM (blocks 0..511) + head_reduce (blocks 512..1023)
    wo_and_weight<<<1024, 256, G_SMEM_BYTES>>>(bo, outO, outW);
}

// round 14
// speedup vs baseline: 1.3481x; 1.0825x over previous
#include <cuda_runtime.h>
#include <cuda_fp16.h>
#include <cstdint>
#include <math.h>

#define BATCH 4
#define SEQ   2048
#define DIM   1024
#define HEADS 16
#define HD    64
#define MTOT  (BATCH*SEQ)   // 8192

// Scratch (allocation-free rule: __device__ globals)
__device__ __half g_in [3][MTOT*DIM];     // fp16 copies of Q,K,V inputs
__device__ __half g_w  [4][DIM*DIM];      // fp16 copies of Wq,Wk,Wv,Wo
__device__ __half g_qh [MTOT*DIM];        // projected q (pre-scaled 0.125)
__device__ __half g_kh [MTOT*DIM];
__device__ __half g_vh [MTOT*DIM];
__device__ __half g_ohh[MTOT*DIM];        // attention output heads
__device__ float  g_rl [BATCH*HEADS*SEQ];
// exp(scores), FRAGMENT-BLOCKED: tile (bh,tile_t,tile_s) of 16x64 halves
// = 512 words; word addr = tile*512 + word_idx*32 + lane.
__device__ unsigned g_expa[(size_t)BATCH*HEADS*(SEQ/16)*(SEQ/64)*512];

// ---------------------------------------------------------------------------
// helpers
// ---------------------------------------------------------------------------
__device__ __forceinline__ void mma16(float c[4],
    unsigned a0, unsigned a1, unsigned a2, unsigned a3,
    unsigned b0, unsigned b1)
{
    asm volatile(
      "mma.sync.aligned.m16n8k16.row.col.f32.f16.f16.f32 "
      "{%0,%1,%2,%3},{%4,%5,%6,%7},{%8,%9},{%0,%1,%2,%3};"
      : "+f"(c[0]), "+f"(c[1]), "+f"(c[2]), "+f"(c[3])
      : "r"(a0), "r"(a1), "r"(a2), "r"(a3), "r"(b0), "r"(b1));
}
__device__ __forceinline__ void ldmx4(unsigned r[4], unsigned addr)
{
    asm volatile(
      "ldmatrix.sync.aligned.m8n8.x4.shared.b16 {%0,%1,%2,%3}, [%4];"
      : "=r"(r[0]), "=r"(r[1]), "=r"(r[2]), "=r"(r[3]) : "r"(addr));
}
__device__ __forceinline__ void ldmx4t(unsigned r[4], unsigned addr)
{
    asm volatile(
      "ldmatrix.sync.aligned.m8n8.x4.trans.shared.b16 {%0,%1,%2,%3}, [%4];"
      : "=r"(r[0]), "=r"(r[1]), "=r"(r[2]), "=r"(r[3]) : "r"(addr));
}
__device__ __forceinline__ unsigned h2u(__half2 h) { return *(unsigned*)&h; }
__device__ __forceinline__ void cpa16(unsigned dst, const void* src) {
    asm volatile("cp.async.cg.shared.global [%0], [%1], 16;\n" :: "r"(dst), "l"(src));
}
__device__ __forceinline__ uint32_t smem_u32(const void* p) {
    uint32_t a;
    asm("{ .reg .u64 t; cvta.to.shared.u64 t, %1; cvt.u32.u64 %0, t; }"
        : "=r"(a) : "l"(p));
    return a;
}

// ---------------------------------------------------------------------------
// single fp32->fp16 convert covering all 7 tensors (grid.y selects)
// ---------------------------------------------------------------------------
__global__ void __launch_bounds__(256) cvt_all(
    const float* q, const float* k, const float* v,
    const float* wq, const float* wk, const float* wv, const float* wo)
{
    const int y = blockIdx.y;
    const float* src;
    __half* dst;
    int n4;
    switch (y) {
        case 0: src = q;  dst = g_in[0]; n4 = MTOT*DIM/4; break;
        case 1: src = k;  dst = g_in[1]; n4 = MTOT*DIM/4; break;
        case 2: src = v;  dst = g_in[2]; n4 = MTOT*DIM/4; break;
        case 3: src = wq; dst = g_w[0];  n4 = DIM*DIM/4;  break;
        case 4: src = wk; dst = g_w[1];  n4 = DIM*DIM/4;  break;
        case 5: src = wv; dst = g_w[2];  n4 = DIM*DIM/4;  break;
        default: src = wo; dst = g_w[3]; n4 = DIM*DIM/4;  break;
    }
    for (int i = blockIdx.x*256 + threadIdx.x; i < n4; i += gridDim.x*256) {
        float4 f = *(const float4*)(src + (size_t)i*4);
        *(__half2*)(dst + (size_t)i*4)     = __floats2half2_rn(f.x, f.y);
        *(__half2*)(dst + (size_t)i*4 + 2) = __floats2half2_rn(f.z, f.w);
    }
}

// ---------------------------------------------------------------------------
// fp16 NT GEMM body, 4-stage cp.async pipeline, one barrier per k-tile.
// Block tile 128x128, BK=32, 256 threads, warp tile 64x32.
// omode: 0 fp32-out, 1 fp16-out, 2 fp16-out scaled 0.125.
// ---------------------------------------------------------------------------
#define LDH   40
#define G_STB (128*LDH)                 // halves per stage-operand (10240 B)
#define G_SMEM_BYTES (4 * 2 * G_STB * 2)  // 81920

__device__ __forceinline__ void gemm_body(
    const __half* __restrict__ A, const __half* __restrict__ W,
    const float* __restrict__ bias, void* __restrict__ Cv,
    unsigned sb, int m0, int n0, int omode)
{
    const int tid  = threadIdx.x;
    const int lane = tid & 31, warp = tid >> 5;
    const int g = lane >> 2, t = lane & 3;
    const int wm = (warp >> 2) << 6, wn = (warp & 3) << 5;
    const __half* Ab = A + (size_t)m0 * DIM;
    const __half* Wb = W + (size_t)n0 * DIM;

    const int ch0 = tid << 1, ch1 = ch0 + 1;
    const int r0 = ch0 >> 2, c0 = (ch0 & 3) << 3;
    const int r1 = ch1 >> 2, c1 = (ch1 & 3) << 3;
    const unsigned aOff0 = (unsigned)((r0*LDH + c0) << 1);
    const unsigned aOff1 = (unsigned)((r1*LDH + c1) << 1);

    const int aRow = wm + (lane & 15);
    const int aKof = (lane >> 4) << 3;
    const int bRow = wn + ((lane >> 4) << 3) + (lane & 7);
    const int bKof = ((lane >> 3) & 1) << 3;

    float acc[4][4][4];
    #pragma unroll
    for (int i = 0; i < 4; i++)
        #pragma unroll
        for (int j = 0; j < 4; j++)
            #pragma unroll
            for (int v = 0; v < 4; v++) acc[i][j][v] = 0.f;

    #pragma unroll
    for (int s = 0; s < 3; s++) {
        const unsigned stB = (unsigned)(s * 2 * G_STB) << 1;
        const int k0 = s << 5;
        cpa16(sb + stB + aOff0,                    Ab + (size_t)r0 * DIM + k0 + c0);
        cpa16(sb + stB + aOff1,                    Ab + (size_t)r1 * DIM + k0 + c1);
        cpa16(sb + stB + (G_STB << 1) + aOff0,     Wb + (size_t)r0 * DIM + k0 + c0);
        cpa16(sb + stB + (G_STB << 1) + aOff1,     Wb + (size_t)r1 * DIM + k0 + c1);
        asm volatile("cp.async.commit_group;\n");
    }

    for (int kt = 0; kt < 32; kt++) {
        if (kt <= 29)      asm volatile("cp.async.wait_group 2;\n");
        else if (kt == 30) asm volatile("cp.async.wait_group 1;\n");
        else               asm volatile("cp.async.wait_group 0;\n");
        __syncthreads();

        if (kt + 3 < 32) {
            const int s = (kt + 3) & 3;
            const unsigned stB = (unsigned)(s * 2 * G_STB) << 1;
            const int k0 = (kt + 3) << 5;
            cpa16(sb + stB + aOff0,                Ab + (size_t)r0 * DIM + k0 + c0);
            cpa16(sb + stB + aOff1,                Ab + (size_t)r1 * DIM + k0 + c1);
            cpa16(sb + stB + (G_STB << 1) + aOff0, Wb + (size_t)r0 * DIM + k0 + c0);
            cpa16(sb + stB + (G_STB << 1) + aOff1, Wb + (size_t)r1 * DIM + k0 + c1);
            asm volatile("cp.async.commit_group;\n");
        }

        const unsigned aB = sb + ((unsigned)((kt & 3) * 2 * G_STB) << 1);
        const unsigned wB = aB + (G_STB << 1);
        #pragma unroll
        for (int s = 0; s < 2; s++) {
            const int kh = s << 4;
            unsigned af[4][4], bf[4][2];
            #pragma unroll
            for (int mt = 0; mt < 4; mt++)
                ldmx4(af[mt], aB +
                      (unsigned)(((aRow + (mt << 4))*LDH + kh + aKof) << 1));
            #pragma unroll
            for (int p = 0; p < 2; p++) {
                unsigned bx[4];
                ldmx4(bx, wB +
                      (unsigned)(((bRow + (p << 4))*LDH + kh + bKof) << 1));
                bf[2*p][0]   = bx[0]; bf[2*p][1]   = bx[1];
                bf[2*p+1][0] = bx[2]; bf[2*p+1][1] = bx[3];
            }
            #pragma unroll
            for (int mt = 0; mt < 4; mt++)
                #pragma unroll
                for (int nt = 0; nt < 4; nt++)
                    mma16(acc[mt][nt], af[mt][0], af[mt][1], af[mt][2], af[mt][3],
                          bf[nt][0], bf[nt][1]);
        }
    }

    #pragma unroll
    for (int mt = 0; mt < 4; mt++) {
        int r = m0 + wm + (mt << 4) + g;
        #pragma unroll
        for (int nt = 0; nt < 4; nt++) {
            int c = n0 + wn + (nt << 3) + (t << 1);
            float2 bv = *(const float2*)(bias + c);
            float o00 = acc[mt][nt][0] + bv.x, o01 = acc[mt][nt][1] + bv.y;
            float o10 = acc[mt][nt][2] + bv.x, o11 = acc[mt][nt][3] + bv.y;
            if (omode == 0) {
                float* C = (float*)Cv;
                *(float2*)(C + (size_t)r       * DIM + c) = make_float2(o00, o01);
                *(float2*)(C + (size_t)(r + 8) * DIM + c) = make_float2(o10, o11);
            } else {
                const float scl = (omode == 2) ? 0.125f : 1.0f;
                __half* C = (__half*)Cv;
                *(__half2*)(C + (size_t)r       * DIM + c) = __floats2half2_rn(o00*scl, o01*scl);
                *(__half2*)(C + (size_t)(r + 8) * DIM + c) = __floats2half2_rn(o10*scl, o11*scl);
            }
        }
    }
}

// ---------------------------------------------------------------------------
// merged q/k/v projection: grid (8, 64, 3); z selects tensor set
// ---------------------------------------------------------------------------
__global__ void __launch_bounds__(256,2) gemm_proj(
    const float* __restrict__ bq, const float* __restrict__ bk,
    const float* __restrict__ bv)
{
    extern __shared__ __half smh[];
    const unsigned sb = smem_u32(smh);
    const int z = blockIdx.z;
    const float* bias = (z == 0) ? bq : (z == 1) ? bk : bv;
    __half* C = (z == 0) ? g_qh : (z == 1) ? g_kh : g_vh;
    gemm_body(g_in[z], g_w[z], bias, C, sb,
              blockIdx.y << 7, blockIdx.x << 7, (z == 0) ? 2 : 1);
}

// ---------------------------------------------------------------------------
// fused Wo-GEMM + head_reduce fat kernel, INTERLEAVED block mapping:
// even blocks -> GEMM tile (idx>>1), odd blocks -> reduce tile (idx>>1).
// Every wave mixes tensor-bound and DRAM-bound work.
// ---------------------------------------------------------------------------
__global__ void __launch_bounds__(256,2) wo_and_weight(
    const float* __restrict__ bo, float* __restrict__ outO,
    float* __restrict__ outW)
{
    extern __shared__ __half smh[];
    const int gidx = blockIdx.x >> 1;
    if ((blockIdx.x & 1) == 0) {
        const unsigned sb = smem_u32(smh);
        gemm_body(g_ohh, g_w[3], bo, outO, sb,
                  (gidx >> 3) << 7, (gidx & 7) << 7, 0);
        return;
    }

    // ---- head_reduce body (tr in dynamic smem: [8][16][66] floats) ----
    float* trb = (float*)smh;
    const int lane = threadIdx.x & 31, warp = threadIdx.x >> 5;
    const int b = gidx >> 7, tile_t = gidx & 127;
    const int r = (lane & 7) + (((lane >> 3) & 1) << 3);
    const int cbase = (lane >> 4) << 3;
    const float invH = 1.0f / (float)HEADS;
    float* tr = trb + warp * 16 * 66;

    for (int ts = warp; ts < SEQ/64; ts += 8) {
        float2 acc[4][4];
        #pragma unroll
        for (int k = 0; k < 4; k++)
            #pragma unroll
            for (int j = 0; j < 4; j++) acc[k][j] = make_float2(0.f, 0.f);

        for (int h = 0; h < HEADS; h++) {
            const int bh = b * HEADS + h;
            const size_t tb4 = ((((size_t)bh*(SEQ/16) + tile_t)*(SEQ/64) + ts)*512) >> 2;
            const uint4* p = (const uint4*)g_expa + tb4 + lane;
            const float rl = __ldg(&g_rl[(size_t)bh*SEQ + (tile_t << 4) + r]);
            #pragma unroll
            for (int k = 0; k < 4; k++) {
                uint4 u = __ldg(p + (k << 5));
                float2 f0 = __half22float2(*(__half2*)&u.x);
                float2 f1 = __half22float2(*(__half2*)&u.y);
                float2 f2 = __half22float2(*(__half2*)&u.z);
                float2 f3 = __half22float2(*(__half2*)&u.w);
                acc[k][0].x += f0.x*rl; acc[k][0].y += f0.y*rl;
                acc[k][1].x += f1.x*rl; acc[k][1].y += f1.y*rl;
                acc[k][2].x += f2.x*rl; acc[k][2].y += f2.y*rl;
                acc[k][3].x += f3.x*rl; acc[k][3].y += f3.y*rl;
            }
        }

        #pragma unroll
        for (int k = 0; k < 4; k++)
            #pragma unroll
            for (int j = 0; j < 4; j++) {
                const int c = cbase + (k << 4) + (j << 1);
                tr[r*66 + c]     = acc[k][j].x * invH;
                tr[r*66 + c + 1] = acc[k][j].y * invH;
            }
        __syncwarp();
        #pragma unroll
        for (int rr = 0; rr < 16; rr++) {
            float2 v = *(float2*)&tr[rr*66 + (lane << 1)];
            *(float2*)(outW + ((size_t)b*SEQ + (tile_t<<4) + rr)*SEQ + (ts<<6) + (lane<<1)) = v;
        }
        __syncwarp();
    }
}

// ---------------------------------------------------------------------------
// attn_o: 8 warps x 16 rows (128 t-rows/block, grid 1024x... blocks),
// <=128 regs -> 2 CTAs/SM (16 warps). Fragment-blocked coalesced expa stores.
// ---------------------------------------------------------------------------
#define LDK 72

__global__ void __launch_bounds__(256,2) attn_o_fp16()
{
    __shared__ __half Ks[2][64*LDK];
    __shared__ __half Vs[2][64*LDK];

    const int tid  = threadIdx.x;
    const int lane = tid & 31, warp = tid >> 5;
    const int g = lane >> 2, t = lane & 3;
    const int t0 = blockIdx.x << 7;                 // 128 rows per block
    const int bh = blockIdx.y;
    const int b = bh >> 4, h = bh & 15;
    const size_t base = (size_t)b * SEQ * DIM + (size_t)h * HD;
    const __half* qb = g_qh + base;
    const __half* kb = g_kh + base;
    const __half* vb = g_vh + base;
    const int row0 = t0 + (warp << 4) + g;          // lane's base row
    const int tile_t = (t0 >> 4) + warp;            // warp's 16-row expa tile
    unsigned* ebw = g_expa + ((size_t)bh*(SEQ/16) + tile_t)*(SEQ/64)*512 + lane;

    // Q fragments (one m-frag): 16 regs
    unsigned qf[4][4];
    #pragma unroll
    for (int ks = 0; ks < 4; ks++) {
        const int c0 = (ks << 4) + (t << 1);
        qf[ks][0] = *(const unsigned*)(qb + (size_t)row0       * DIM + c0);
        qf[ks][1] = *(const unsigned*)(qb + (size_t)(row0 + 8) * DIM + c0);
        qf[ks][2] = *(const unsigned*)(qb + (size_t)row0       * DIM + c0 + 8);
        qf[ks][3] = *(const unsigned*)(qb + (size_t)(row0 + 8) * DIM + c0 + 8);
    }

    float oacc[8][4];
    #pragma unroll
    for (int i = 0; i < 8; i++)
        #pragma unroll
        for (int v = 0; v < 4; v++) oacc[i][v] = 0.f;
    float lp0 = 0.f, lp1 = 0.f;

    const unsigned ksb[2] = { smem_u32(Ks[0]), smem_u32(Ks[1]) };
    const unsigned vsb[2] = { smem_u32(Vs[0]), smem_u32(Vs[1]) };
    const int mi = lane >> 3, mj = lane & 7;

    const int r0c = tid >> 3,         c0c = (tid & 7) << 3;
    const int r1c = (tid + 256) >> 3, c1c = c0c;

    cpa16(ksb[0] + ((r0c*LDK + c0c) << 1), kb + (size_t)r0c * DIM + c0c);
    cpa16(ksb[0] + ((r1c*LDK + c1c) << 1), kb + (size_t)r1c * DIM + c1c);
    cpa16(vsb[0] + ((r0c*LDK + c0c) << 1), vb + (size_t)r0c * DIM + c0c);
    cpa16(vsb[0] + ((r1c*LDK + c1c) << 1), vb + (size_t)r1c * DIM + c1c);
    asm volatile("cp.async.commit_group;\n");

    for (int i = 0; i < SEQ/64; i++) {
        const int st = i & 1;
        if (i + 1 < SEQ/64) {
            const int ns = (i + 1) & 1;
            const size_t nb = (size_t)((i + 1) << 6) * DIM;
            cpa16(ksb[ns] + ((r0c*LDK + c0c) << 1), kb + nb + (size_t)r0c * DIM + c0c);
            cpa16(ksb[ns] + ((r1c*LDK + c1c) << 1), kb + nb + (size_t)r1c * DIM + c1c);
            cpa16(vsb[ns] + ((r0c*LDK + c0c) << 1), vb + nb + (size_t)r0c * DIM + c0c);
            cpa16(vsb[ns] + ((r1c*LDK + c1c) << 1), vb + nb + (size_t)r1c * DIM + c1c);
            asm volatile("cp.async.commit_group;\n");
            asm volatile("cp.async.wait_group 1;\n");
        } else {
            asm volatile("cp.async.wait_group 0;\n");
        }
        __syncthreads();

        const __half* ksp = Ks[st];
        unsigned* eb = ebw + (size_t)i * 512;

        // ---- scores = Q K^T : 16 x 64 ----
        float sc[8][4];
        #pragma unroll
        for (int x = 0; x < 8; x++)
            #pragma unroll
            for (int v = 0; v < 4; v++) sc[x][v] = 0.f;
        #pragma unroll
        for (int ks = 0; ks < 4; ks++) {
            const int kc = (ks << 4) + (t << 1);
            #pragma unroll
            for (int nt = 0; nt < 8; nt++) {
                unsigned b0 = *(const unsigned*)&ksp[((nt<<3)+g)*LDK + kc];
                unsigned b1 = *(const unsigned*)&ksp[((nt<<3)+g)*LDK + kc + 8];
                mma16(sc[nt], qf[ks][0], qf[ks][1], qf[ks][2], qf[ks][3], b0, b1);
            }
        }

        // ---- exp; blocked-coalesced expa stores; pack AV A-fragments ----
        unsigned ph[8][2];
        #pragma unroll
        for (int nt = 0; nt < 8; nt++) {
            float e0 = __expf(fminf(sc[nt][0], 11.f));
            float e1 = __expf(fminf(sc[nt][1], 11.f));
            float e2 = __expf(fminf(sc[nt][2], 11.f));
            float e3 = __expf(fminf(sc[nt][3], 11.f));
            lp0 += e0 + e1;
            lp1 += e2 + e3;
            ph[nt][0] = h2u(__floats2half2_rn(e0, e1));
            ph[nt][1] = h2u(__floats2half2_rn(e2, e3));
            eb[(2*nt    ) << 5] = ph[nt][0];
            eb[(2*nt + 1) << 5] = ph[nt][1];
        }

        // ---- O += P V ----
        #pragma unroll
        for (int ks2 = 0; ks2 < 4; ks2++) {
            const unsigned a0 = ph[2*ks2][0],   a1 = ph[2*ks2][1];
            const unsigned a2 = ph[2*ks2+1][0], a3 = ph[2*ks2+1][1];
            #pragma unroll
            for (int p = 0; p < 4; p++) {
                const int vrow = (ks2 << 4) + ((mi & 1) << 3) + mj;
                const int vcol = (p << 4) + ((mi >> 1) << 3);
                unsigned r[4];
                ldmx4t(r, vsb[st] + (unsigned)((vrow*LDK + vcol) << 1));
                mma16(oacc[2*p],   a0, a1, a2, a3, r[0], r[1]);
                mma16(oacc[2*p+1], a0, a1, a2, a3, r[2], r[3]);
            }
        }
        __syncthreads();
    }

    // ---- row sums over the quad; rl; normalized O (fp16) ----
    lp0 += __shfl_xor_sync(0xffffffffu, lp0, 1);
    lp0 += __shfl_xor_sync(0xffffffffu, lp0, 2);
    lp1 += __shfl_xor_sync(0xffffffffu, lp1, 1);
    lp1 += __shfl_xor_sync(0xffffffffu, lp1, 2);
    const float rl0 = 1.0f / lp0;
    const float rl1 = 1.0f / lp1;
    if (t == 0) {
        g_rl[(size_t)bh * SEQ + row0]     = rl0;
        g_rl[(size_t)bh * SEQ + row0 + 8] = rl1;
    }
    #pragma unroll
    for (int nt = 0; nt < 8; nt++) {
        const int c = h*HD + (nt << 3) + (t << 1);
        *(__half2*)(g_ohh + (size_t)(b*SEQ + row0)     * DIM + c) =
            __floats2half2_rn(oacc[nt][0]*rl0, oacc[nt][1]*rl0);
        *(__half2*)(g_ohh + (size_t)(b*SEQ + row0 + 8) * DIM + c) =
            __floats2half2_rn(oacc[nt][2]*rl1, oacc[nt][3]*rl1);
    }
}

// ---------------------------------------------------------------------------
extern "C" void kernel_launch(void* const* d_in, const int* in_sizes, int n_in,
                              void* d_out, int out_size)
{
    const float* Q  = (const float*)d_in[0];
    const float* K  = (const float*)d_in[1];
    const float* V  = (const float*)d_in[2];
    const float* Wq = (const float*)d_in[3];
    const float* bq = (const float*)d_in[4];
    const float* Wk = (const float*)d_in[5];
    const float* bk = (const float*)d_in[6];
    const float* Wv = (const float*)d_in[7];
    const float* bv = (const float*)d_in[8];
    const float* Wo = (const float*)d_in[9];
    const float* bo = (const float*)d_in[10];

    float* outO = (float*)d_out;                       // [B,T,D]
    float* outW = outO + (size_t)BATCH * SEQ * DIM;    // [B,T,T]

    cudaFuncSetAttribute(gemm_proj,     cudaFuncAttributeMaxDynamicSharedMemorySize, G_SMEM_BYTES);
    cudaFuncSetAttribute(wo_and_weight, cudaFuncAttributeMaxDynamicSharedMemorySize, G_SMEM_BYTES);

    cvt_all<<<dim3(256, 7), 256>>>(Q, K, V, Wq, Wk, Wv, Wo);

    // merged q/k/v projections: grid (8, 64, 3)
    gemm_proj<<<dim3(DIM/128, MTOT/128, 3), 256, G_SMEM_BYTES>>>(bq, bk, bv);

    attn_o_fp16<<<dim3(SEQ/128, BATCH*HEADS), 256>>>();

    // fused+interleaved Wo-GEMM (even blocks) + head_reduce (odd blocks)
    wo_and_weight<<<1024, 256, G_SMEM_BYTES>>>(bo, outO, outW);
}